// round 1
// baseline (speedup 1.0000x reference)
#include <cuda_runtime.h>
#include <math.h>

#define N_ATOMS 10000
#define N_EDGES 150000
#define NB 128
#define NI 3
#define N_RBF 20
#define CUTOFF 5.0f
#define EPSV 1e-8f
#define BATCH 64
#define TILE 8

// ---------------- device scratch (static, no allocation) ----------------
__device__ float g_q   [N_ATOMS * NB];          // (atoms,128)
__device__ float g_mu  [N_ATOMS * 3 * NB];      // (atoms,3,128)
__device__ float g_x   [N_ATOMS * 3 * NB];      // per-atom MLP output (atoms,384)
__device__ float g_dq  [N_ATOMS * NB];          // edge-scatter accumulator
__device__ float g_dmu [N_ATOMS * 3 * NB];      // edge-scatter accumulator
__device__ float g_phif[N_EDGES * N_RBF];       // phi * fcut per edge
__device__ float g_fc  [N_EDGES];               // fcut per edge
__device__ float g_dir [N_EDGES * 3];           // unit direction per edge

__device__ __forceinline__ float silu_f(float v) {
    return v / (1.0f + expf(-v));
}

// ---------------- edge geometry precompute ----------------
__global__ void k_init_edges(const float* __restrict__ pos,
                             const int* __restrict__ idx_i,
                             const int* __restrict__ idx_j) {
    int e = blockIdx.x * blockDim.x + threadIdx.x;
    if (e >= N_EDGES) return;
    int i = idx_i[e], j = idx_j[e];
    float rx = pos[j * 3 + 0] - pos[i * 3 + 0];
    float ry = pos[j * 3 + 1] - pos[i * 3 + 1];
    float rz = pos[j * 3 + 2] - pos[i * 3 + 2];
    float d  = sqrtf(rx * rx + ry * ry + rz * rz);
    float inv = 1.0f / d;
    g_dir[e * 3 + 0] = rx * inv;
    g_dir[e * 3 + 1] = ry * inv;
    g_dir[e * 3 + 2] = rz * inv;
    float fc = (d < CUTOFF) ? 0.5f * (cosf(d * (float)M_PI / CUTOFF) + 1.0f) : 0.0f;
    g_fc[e] = fc;
    const float width = CUTOFF / (float)(N_RBF - 1);
    const float coeff = -0.5f / (width * width);
    #pragma unroll
    for (int r = 0; r < N_RBF; r++) {
        float dd = d - (float)r * width;
        g_phif[e * N_RBF + r] = expf(coeff * dd * dd) * fc;
    }
}

// ---------------- atom init: q = emb[z], mu = 0, y = 0 ----------------
__global__ void k_init_atoms(const float* __restrict__ emb,
                             const int* __restrict__ z,
                             float* __restrict__ y_out) {
    int a = blockIdx.x;
    int t = threadIdx.x;
    g_q[a * NB + t] = emb[z[a] * NB + t];
    #pragma unroll
    for (int d = 0; d < 3; d++)
        g_mu[a * 3 * NB + d * NB + t] = 0.0f;
    if (a == 0 && t < BATCH) y_out[t] = 0.0f;
}

// ---------------- per-atom input MLP: x = silu(q@W1+b1)@W2+b2 ----------------
// also zeroes the edge-scatter accumulators for this iteration
__global__ void __launch_bounds__(128) k_atoms_x(
        const float* __restrict__ ic1W, const float* __restrict__ ic1b,
        const float* __restrict__ ic2W, const float* __restrict__ ic2b,
        int it) {
    __shared__ float qs[TILE][NB];
    __shared__ float hs[TILE][NB];
    int t  = threadIdx.x;
    int a0 = blockIdx.x * TILE;

    #pragma unroll
    for (int a = 0; a < TILE; a++) {
        qs[a][t] = g_q[(a0 + a) * NB + t];
        g_dq[(a0 + a) * NB + t] = 0.0f;
        #pragma unroll
        for (int d = 0; d < 3; d++)
            g_dmu[(a0 + a) * 3 * NB + d * NB + t] = 0.0f;
    }
    __syncthreads();

    const float* W1 = ic1W + (size_t)it * NB * NB;
    float acc[TILE];
    float b1 = ic1b[it * NB + t];
    #pragma unroll
    for (int a = 0; a < TILE; a++) acc[a] = b1;
    for (int k = 0; k < NB; k++) {
        float w = W1[k * NB + t];
        #pragma unroll
        for (int a = 0; a < TILE; a++) acc[a] += qs[a][k] * w;
    }
    #pragma unroll
    for (int a = 0; a < TILE; a++) hs[a][t] = silu_f(acc[a]);
    __syncthreads();

    const float* W2 = ic2W + (size_t)it * NB * 3 * NB;
    float c0[TILE], c1[TILE], c2[TILE];
    float b20 = ic2b[it * 3 * NB + t];
    float b21 = ic2b[it * 3 * NB + NB + t];
    float b22 = ic2b[it * 3 * NB + 2 * NB + t];
    #pragma unroll
    for (int a = 0; a < TILE; a++) { c0[a] = b20; c1[a] = b21; c2[a] = b22; }
    for (int k = 0; k < NB; k++) {
        float w0 = W2[k * 384 + t];
        float w1 = W2[k * 384 + NB + t];
        float w2 = W2[k * 384 + 2 * NB + t];
        #pragma unroll
        for (int a = 0; a < TILE; a++) {
            float h = hs[a][k];
            c0[a] += h * w0; c1[a] += h * w1; c2[a] += h * w2;
        }
    }
    #pragma unroll
    for (int a = 0; a < TILE; a++) {
        g_x[(a0 + a) * 384 + t]          = c0[a];
        g_x[(a0 + a) * 384 + NB + t]     = c1[a];
        g_x[(a0 + a) * 384 + 2 * NB + t] = c2[a];
    }
}

// ---------------- edge kernel: filters * x[j], scatter to dq/dmu ----------------
__global__ void __launch_bounds__(128) k_edges(
        const float* __restrict__ fW, const float* __restrict__ fb,
        const int* __restrict__ idx_i, const int* __restrict__ idx_j,
        int it) {
    __shared__ float fWs[N_RBF * 384];
    __shared__ float fbs[384];
    int t = threadIdx.x;
    for (int idx = t; idx < N_RBF * 384; idx += 128) {
        int r = idx / 384, c = idx % 384;
        fWs[idx] = fW[r * (NI * 3 * NB) + it * 384 + c];
    }
    for (int idx = t; idx < 384; idx += 128)
        fbs[idx] = fb[it * 384 + idx];
    __syncthreads();

    for (int e = blockIdx.x; e < N_EDGES; e += gridDim.x) {
        int j  = idx_j[e];
        int ia = idx_i[e];
        float fc = g_fc[e];
        float w0 = fbs[t] * fc;
        float w1 = fbs[NB + t] * fc;
        float w2 = fbs[2 * NB + t] * fc;
        #pragma unroll
        for (int r = 0; r < N_RBF; r++) {
            float p = g_phif[e * N_RBF + r];
            w0 += p * fWs[r * 384 + t];
            w1 += p * fWs[r * 384 + NB + t];
            w2 += p * fWs[r * 384 + 2 * NB + t];
        }
        const float* xj = g_x + (size_t)j * 384;
        float vq = w0 * xj[t];
        float vR = w1 * xj[NB + t];
        float vM = w2 * xj[2 * NB + t];
        atomicAdd(&g_dq[ia * NB + t], vq);
        float dx = g_dir[e * 3 + 0], dy = g_dir[e * 3 + 1], dz = g_dir[e * 3 + 2];
        const float* muj = g_mu + (size_t)j * 3 * NB;
        atomicAdd(&g_dmu[ia * 3 * NB + t],          vR * dx + vM * muj[t]);
        atomicAdd(&g_dmu[ia * 3 * NB + NB + t],     vR * dy + vM * muj[NB + t]);
        atomicAdd(&g_dmu[ia * 3 * NB + 2 * NB + t], vR * dz + vM * muj[2 * NB + t]);
    }
}

// ---------------- per-atom update: q+=dq, mu+=dmu, mix + ctx MLP ----------------
__global__ void __launch_bounds__(128) k_atoms_update(
        const float* __restrict__ mixW,
        const float* __restrict__ c1W, const float* __restrict__ c1b,
        const float* __restrict__ c2W, const float* __restrict__ c2b,
        int it) {
    __shared__ float qs[TILE][NB];
    __shared__ float mus[TILE][3][NB];
    __shared__ float ctxs[TILE][2 * NB];
    __shared__ float hs[TILE][NB];
    int t  = threadIdx.x;
    int a0 = blockIdx.x * TILE;

    #pragma unroll
    for (int a = 0; a < TILE; a++) {
        int g = a0 + a;
        qs[a][t] = g_q[g * NB + t] + g_dq[g * NB + t];
        #pragma unroll
        for (int d = 0; d < 3; d++)
            mus[a][d][t] = g_mu[g * 3 * NB + d * NB + t] + g_dmu[g * 3 * NB + d * NB + t];
    }
    __syncthreads();

    // mix: mu @ mix_W -> mu_V (col t), mu_Wc (col 128+t)
    const float* MW = mixW + (size_t)it * NB * 2 * NB;
    float v[TILE][3], w[TILE][3];
    #pragma unroll
    for (int a = 0; a < TILE; a++)
        #pragma unroll
        for (int d = 0; d < 3; d++) { v[a][d] = 0.0f; w[a][d] = 0.0f; }
    for (int k = 0; k < NB; k++) {
        float wv = MW[k * 256 + t];
        float ww = MW[k * 256 + NB + t];
        #pragma unroll
        for (int a = 0; a < TILE; a++) {
            #pragma unroll
            for (int d = 0; d < 3; d++) {
                float m = mus[a][d][k];
                v[a][d] += m * wv;
                w[a][d] += m * ww;
            }
        }
    }
    float s[TILE];
    #pragma unroll
    for (int a = 0; a < TILE; a++) {
        float n2 = v[a][0] * v[a][0] + v[a][1] * v[a][1] + v[a][2] * v[a][2];
        float vn = sqrtf(n2 + EPSV);
        s[a] = v[a][0] * w[a][0] + v[a][1] * w[a][1] + v[a][2] * w[a][2];
        ctxs[a][t]      = qs[a][t];
        ctxs[a][NB + t] = vn;
    }
    __syncthreads();

    // ctx1: (256 -> 128), silu
    const float* W1 = c1W + (size_t)it * 2 * NB * NB;
    float acc[TILE];
    float b1 = c1b[it * NB + t];
    #pragma unroll
    for (int a = 0; a < TILE; a++) acc[a] = b1;
    for (int k = 0; k < 2 * NB; k++) {
        float ww = W1[k * NB + t];
        #pragma unroll
        for (int a = 0; a < TILE; a++) acc[a] += ctxs[a][k] * ww;
    }
    #pragma unroll
    for (int a = 0; a < TILE; a++) hs[a][t] = silu_f(acc[a]);
    __syncthreads();

    // ctx2: (128 -> 384) -> dq_in / dmu_in / dqmu_in
    const float* W2 = c2W + (size_t)it * NB * 3 * NB;
    float aq[TILE], am[TILE], aqm[TILE];
    float b20 = c2b[it * 3 * NB + t];
    float b21 = c2b[it * 3 * NB + NB + t];
    float b22 = c2b[it * 3 * NB + 2 * NB + t];
    #pragma unroll
    for (int a = 0; a < TILE; a++) { aq[a] = b20; am[a] = b21; aqm[a] = b22; }
    for (int k = 0; k < NB; k++) {
        float w0 = W2[k * 384 + t];
        float w1 = W2[k * 384 + NB + t];
        float w2 = W2[k * 384 + 2 * NB + t];
        #pragma unroll
        for (int a = 0; a < TILE; a++) {
            float h = hs[a][k];
            aq[a] += h * w0; am[a] += h * w1; aqm[a] += h * w2;
        }
    }
    #pragma unroll
    for (int a = 0; a < TILE; a++) {
        int g = a0 + a;
        g_q[g * NB + t] = qs[a][t] + aq[a] + aqm[a] * s[a];
        #pragma unroll
        for (int d = 0; d < 3; d++)
            g_mu[g * 3 * NB + d * NB + t] = mus[a][d][t] + am[a] * w[a][d];
    }
}

// ---------------- output head: 128->128->128->1, segment sum ----------------
__global__ void __launch_bounds__(128) k_head(
        const float* __restrict__ o1W, const float* __restrict__ o1b,
        const float* __restrict__ o2W, const float* __restrict__ o2b,
        const float* __restrict__ o3W, const float* __restrict__ o3b,
        const int* __restrict__ idx_m, float* __restrict__ y) {
    __shared__ float qs[TILE][NB];
    __shared__ float h1[TILE][NB];
    __shared__ float h2[TILE][NB];
    int t  = threadIdx.x;
    int a0 = blockIdx.x * TILE;
    #pragma unroll
    for (int a = 0; a < TILE; a++) qs[a][t] = g_q[(a0 + a) * NB + t];
    __syncthreads();

    float acc[TILE];
    float b = o1b[t];
    #pragma unroll
    for (int a = 0; a < TILE; a++) acc[a] = b;
    for (int k = 0; k < NB; k++) {
        float w = o1W[k * NB + t];
        #pragma unroll
        for (int a = 0; a < TILE; a++) acc[a] += qs[a][k] * w;
    }
    #pragma unroll
    for (int a = 0; a < TILE; a++) h1[a][t] = silu_f(acc[a]);
    __syncthreads();

    b = o2b[t];
    #pragma unroll
    for (int a = 0; a < TILE; a++) acc[a] = b;
    for (int k = 0; k < NB; k++) {
        float w = o2W[k * NB + t];
        #pragma unroll
        for (int a = 0; a < TILE; a++) acc[a] += h1[a][k] * w;
    }
    #pragma unroll
    for (int a = 0; a < TILE; a++) h2[a][t] = silu_f(acc[a]);
    __syncthreads();

    if (t < TILE) {
        float sum = o3b[0];
        for (int k = 0; k < NB; k++) sum += h2[t][k] * o3W[k];
        atomicAdd(&y[idx_m[a0 + t]], sum);
    }
}

// ---------------- copy mu into output ----------------
__global__ void k_copy_mu(float* __restrict__ out) {
    int idx = blockIdx.x * blockDim.x + threadIdx.x;
    if (idx < N_ATOMS * 3 * NB) out[idx] = g_mu[idx];
}

// ---------------- launch ----------------
extern "C" void kernel_launch(void* const* d_in, const int* in_sizes, int n_in,
                              void* d_out, int out_size) {
    const float* positions = (const float*)d_in[0];
    const float* emb  = (const float*)d_in[1];
    const float* fW   = (const float*)d_in[2];
    const float* fb   = (const float*)d_in[3];
    const float* ic1W = (const float*)d_in[4];
    const float* ic1b = (const float*)d_in[5];
    const float* ic2W = (const float*)d_in[6];
    const float* ic2b = (const float*)d_in[7];
    const float* mixW = (const float*)d_in[8];
    const float* c1W  = (const float*)d_in[9];
    const float* c1b  = (const float*)d_in[10];
    const float* c2W  = (const float*)d_in[11];
    const float* c2b  = (const float*)d_in[12];
    const float* o1W  = (const float*)d_in[13];
    const float* o1b  = (const float*)d_in[14];
    const float* o2W  = (const float*)d_in[15];
    const float* o2b  = (const float*)d_in[16];
    const float* o3W  = (const float*)d_in[17];
    const float* o3b  = (const float*)d_in[18];
    const int* z      = (const int*)d_in[19];
    const int* idx_i  = (const int*)d_in[20];
    const int* idx_j  = (const int*)d_in[21];
    const int* idx_m  = (const int*)d_in[22];
    float* out = (float*)d_out;   // layout: y[64], then mu[10000*3*128]

    k_init_edges<<<(N_EDGES + 255) / 256, 256>>>(positions, idx_i, idx_j);
    k_init_atoms<<<N_ATOMS, 128>>>(emb, z, out);

    for (int it = 0; it < NI; it++) {
        k_atoms_x<<<N_ATOMS / TILE, 128>>>(ic1W, ic1b, ic2W, ic2b, it);
        k_edges<<<1024, 128>>>(fW, fb, idx_i, idx_j, it);
        k_atoms_update<<<N_ATOMS / TILE, 128>>>(mixW, c1W, c1b, c2W, c2b, it);
    }

    k_head<<<N_ATOMS / TILE, 128>>>(o1W, o1b, o2W, o2b, o3W, o3b, idx_m, out);
    k_copy_mu<<<(N_ATOMS * 3 * NB + 255) / 256, 256>>>(out + BATCH);
}

// round 2
// speedup vs baseline: 1.3641x; 1.3641x over previous
#include <cuda_runtime.h>
#include <math.h>

#define N_ATOMS 10000
#define N_EDGES 150000
#define NB 128
#define NI 3
#define N_RBF 20
#define CUTOFF 5.0f
#define EPSV 1e-8f
#define BATCH 64
#define TILE 8
#define AT 16            // atoms per gather block (two halves of 8)

// ---------------- device scratch (static, no allocation) ----------------
__device__ float g_q   [N_ATOMS * NB];
__device__ float g_mu  [N_ATOMS * 3 * NB];
__device__ float g_x   [N_ATOMS * 3 * NB];
__device__ float g_dq  [N_ATOMS * NB];
__device__ float g_dmu [N_ATOMS * 3 * NB];
__device__ float g_phif[N_EDGES * N_RBF];
__device__ float g_fc  [N_EDGES];
__device__ float g_dir [N_EDGES * 3];
// CSR by destination atom (idx_i)
__device__ int   g_cnt [N_ATOMS];
__device__ int   g_ofs [N_ATOMS + 1];
__device__ int   g_cur [N_ATOMS];
__device__ int   g_csr [N_EDGES];

__device__ __forceinline__ float silu_f(float v) {
    return v / (1.0f + expf(-v));
}

// ---------------- edge geometry precompute ----------------
__global__ void k_init_edges(const float* __restrict__ pos,
                             const int* __restrict__ idx_i,
                             const int* __restrict__ idx_j) {
    int e = blockIdx.x * blockDim.x + threadIdx.x;
    if (e >= N_EDGES) return;
    int i = idx_i[e], j = idx_j[e];
    float rx = pos[j * 3 + 0] - pos[i * 3 + 0];
    float ry = pos[j * 3 + 1] - pos[i * 3 + 1];
    float rz = pos[j * 3 + 2] - pos[i * 3 + 2];
    float d  = sqrtf(rx * rx + ry * ry + rz * rz);
    float inv = 1.0f / d;
    g_dir[e * 3 + 0] = rx * inv;
    g_dir[e * 3 + 1] = ry * inv;
    g_dir[e * 3 + 2] = rz * inv;
    float fc = (d < CUTOFF) ? 0.5f * (cosf(d * (float)M_PI / CUTOFF) + 1.0f) : 0.0f;
    g_fc[e] = fc;
    const float width = CUTOFF / (float)(N_RBF - 1);
    const float coeff = -0.5f / (width * width);
    #pragma unroll
    for (int r = 0; r < N_RBF; r++) {
        float dd = d - (float)r * width;
        g_phif[e * N_RBF + r] = expf(coeff * dd * dd) * fc;
    }
}

// ---------------- CSR build ----------------
__global__ void k_zero_cnt() {
    int a = blockIdx.x * blockDim.x + threadIdx.x;
    if (a < N_ATOMS) g_cnt[a] = 0;
}
__global__ void k_hist(const int* __restrict__ idx_i) {
    int e = blockIdx.x * blockDim.x + threadIdx.x;
    if (e < N_EDGES) atomicAdd(&g_cnt[idx_i[e]], 1);
}
__global__ void __launch_bounds__(1024) k_scan() {
    __shared__ int partial[1024];
    int t = threadIdx.x;
    int base = t * 10;
    int local[10];
    int s = 0;
    #pragma unroll
    for (int k = 0; k < 10; k++) {
        int idx = base + k;
        int c = (idx < N_ATOMS) ? g_cnt[idx] : 0;
        local[k] = s;
        s += c;
    }
    partial[t] = s;
    __syncthreads();
    for (int off = 1; off < 1024; off <<= 1) {
        int v = partial[t];
        int u = (t >= off) ? partial[t - off] : 0;
        __syncthreads();
        partial[t] = v + u;
        __syncthreads();
    }
    int pre = (t > 0) ? partial[t - 1] : 0;
    #pragma unroll
    for (int k = 0; k < 10; k++) {
        int idx = base + k;
        if (idx < N_ATOMS) {
            int o = pre + local[k];
            g_ofs[idx] = o;
            g_cur[idx] = o;
        }
    }
    if (t == 1023) g_ofs[N_ATOMS] = partial[1023];
}
__global__ void k_fill(const int* __restrict__ idx_i) {
    int e = blockIdx.x * blockDim.x + threadIdx.x;
    if (e < N_EDGES) {
        int pos = atomicAdd(&g_cur[idx_i[e]], 1);
        g_csr[pos] = e;
    }
}

// ---------------- atom init: q = emb[z], mu = 0, y = 0 ----------------
__global__ void k_init_atoms(const float* __restrict__ emb,
                             const int* __restrict__ z,
                             float* __restrict__ y_out) {
    int a = blockIdx.x;
    int t = threadIdx.x;
    g_q[a * NB + t] = emb[z[a] * NB + t];
    #pragma unroll
    for (int d = 0; d < 3; d++)
        g_mu[a * 3 * NB + d * NB + t] = 0.0f;
    if (a == 0 && t < BATCH) y_out[t] = 0.0f;
}

// ---------------- per-atom input MLP: x = silu(q@W1+b1)@W2+b2 ----------------
__global__ void __launch_bounds__(128) k_atoms_x(
        const float* __restrict__ ic1W, const float* __restrict__ ic1b,
        const float* __restrict__ ic2W, const float* __restrict__ ic2b,
        int it) {
    __shared__ float qs[TILE][NB];
    __shared__ float hs[TILE][NB];
    int t  = threadIdx.x;
    int a0 = blockIdx.x * TILE;

    #pragma unroll
    for (int a = 0; a < TILE; a++)
        qs[a][t] = g_q[(a0 + a) * NB + t];
    __syncthreads();

    const float* W1 = ic1W + (size_t)it * NB * NB;
    float acc[TILE];
    float b1 = ic1b[it * NB + t];
    #pragma unroll
    for (int a = 0; a < TILE; a++) acc[a] = b1;
    for (int k = 0; k < NB; k++) {
        float w = W1[k * NB + t];
        #pragma unroll
        for (int a = 0; a < TILE; a++) acc[a] += qs[a][k] * w;
    }
    #pragma unroll
    for (int a = 0; a < TILE; a++) hs[a][t] = silu_f(acc[a]);
    __syncthreads();

    const float* W2 = ic2W + (size_t)it * NB * 3 * NB;
    float c0[TILE], c1[TILE], c2[TILE];
    float b20 = ic2b[it * 3 * NB + t];
    float b21 = ic2b[it * 3 * NB + NB + t];
    float b22 = ic2b[it * 3 * NB + 2 * NB + t];
    #pragma unroll
    for (int a = 0; a < TILE; a++) { c0[a] = b20; c1[a] = b21; c2[a] = b22; }
    for (int k = 0; k < NB; k++) {
        float w0 = W2[k * 384 + t];
        float w1 = W2[k * 384 + NB + t];
        float w2 = W2[k * 384 + 2 * NB + t];
        #pragma unroll
        for (int a = 0; a < TILE; a++) {
            float h = hs[a][k];
            c0[a] += h * w0; c1[a] += h * w1; c2[a] += h * w2;
        }
    }
    #pragma unroll
    for (int a = 0; a < TILE; a++) {
        g_x[(a0 + a) * 384 + t]          = c0[a];
        g_x[(a0 + a) * 384 + NB + t]     = c1[a];
        g_x[(a0 + a) * 384 + 2 * NB + t] = c2[a];
    }
}

// ---------------- edge gather: per destination atom, accumulate messages ----
__global__ void __launch_bounds__(256) k_gather(
        const int* __restrict__ idx_j,
        const float* __restrict__ fW, const float* __restrict__ fb,
        int it) {
    __shared__ float fWs[N_RBF * 384];
    __shared__ float fbs[384];
    int t    = threadIdx.x & 127;   // feature
    int half = threadIdx.x >> 7;    // 0 / 1

    for (int idx = threadIdx.x; idx < N_RBF * 384; idx += 256) {
        int r = idx / 384, c = idx % 384;
        fWs[idx] = fW[r * (NI * 3 * NB) + it * 384 + c];
    }
    for (int idx = threadIdx.x; idx < 384; idx += 256)
        fbs[idx] = fb[it * 384 + idx];
    __syncthreads();

    float fb0 = fbs[t], fb1 = fbs[NB + t], fb2 = fbs[2 * NB + t];
    int abase = blockIdx.x * AT + half * (AT / 2);

    #pragma unroll 1
    for (int a = 0; a < AT / 2; a++) {
        int i = abase + a;
        int beg = g_ofs[i], end = g_ofs[i + 1];
        float accq = 0.0f, m0 = 0.0f, m1 = 0.0f, m2 = 0.0f;
        for (int k = beg; k < end; k++) {
            int e = g_csr[k];
            int j = idx_j[e];
            float fc = g_fc[e];
            const float4* ph4 = (const float4*)(g_phif + (size_t)e * N_RBF);
            float p[N_RBF];
            #pragma unroll
            for (int r4 = 0; r4 < N_RBF / 4; r4++) {
                float4 v = ph4[r4];
                p[r4 * 4 + 0] = v.x; p[r4 * 4 + 1] = v.y;
                p[r4 * 4 + 2] = v.z; p[r4 * 4 + 3] = v.w;
            }
            float w0 = fb0 * fc, w1 = fb1 * fc, w2 = fb2 * fc;
            #pragma unroll
            for (int r = 0; r < N_RBF; r++) {
                w0 += p[r] * fWs[r * 384 + t];
                w1 += p[r] * fWs[r * 384 + NB + t];
                w2 += p[r] * fWs[r * 384 + 2 * NB + t];
            }
            const float* xj = g_x + (size_t)j * 384;
            float vq = w0 * xj[t];
            float vR = w1 * xj[NB + t];
            float vM = w2 * xj[2 * NB + t];
            float dx = g_dir[e * 3 + 0], dy = g_dir[e * 3 + 1], dz = g_dir[e * 3 + 2];
            const float* muj = g_mu + (size_t)j * 3 * NB;
            accq += vq;
            m0 += vR * dx + vM * muj[t];
            m1 += vR * dy + vM * muj[NB + t];
            m2 += vR * dz + vM * muj[2 * NB + t];
        }
        g_dq[i * NB + t] = accq;
        g_dmu[i * 3 * NB + t]              = m0;
        g_dmu[i * 3 * NB + NB + t]         = m1;
        g_dmu[i * 3 * NB + 2 * NB + t]     = m2;
    }
}

// ---------------- per-atom update: q+=dq, mu+=dmu, mix + ctx MLP ----------------
__global__ void __launch_bounds__(128) k_atoms_update(
        const float* __restrict__ mixW,
        const float* __restrict__ c1W, const float* __restrict__ c1b,
        const float* __restrict__ c2W, const float* __restrict__ c2b,
        int it) {
    __shared__ float qs[TILE][NB];
    __shared__ float mus[TILE][3][NB];
    __shared__ float ctxs[TILE][2 * NB];
    __shared__ float hs[TILE][NB];
    int t  = threadIdx.x;
    int a0 = blockIdx.x * TILE;

    #pragma unroll
    for (int a = 0; a < TILE; a++) {
        int g = a0 + a;
        qs[a][t] = g_q[g * NB + t] + g_dq[g * NB + t];
        #pragma unroll
        for (int d = 0; d < 3; d++)
            mus[a][d][t] = g_mu[g * 3 * NB + d * NB + t] + g_dmu[g * 3 * NB + d * NB + t];
    }
    __syncthreads();

    const float* MW = mixW + (size_t)it * NB * 2 * NB;
    float v[TILE][3], w[TILE][3];
    #pragma unroll
    for (int a = 0; a < TILE; a++)
        #pragma unroll
        for (int d = 0; d < 3; d++) { v[a][d] = 0.0f; w[a][d] = 0.0f; }
    for (int k = 0; k < NB; k++) {
        float wv = MW[k * 256 + t];
        float ww = MW[k * 256 + NB + t];
        #pragma unroll
        for (int a = 0; a < TILE; a++) {
            #pragma unroll
            for (int d = 0; d < 3; d++) {
                float m = mus[a][d][k];
                v[a][d] += m * wv;
                w[a][d] += m * ww;
            }
        }
    }
    float s[TILE];
    #pragma unroll
    for (int a = 0; a < TILE; a++) {
        float n2 = v[a][0] * v[a][0] + v[a][1] * v[a][1] + v[a][2] * v[a][2];
        float vn = sqrtf(n2 + EPSV);
        s[a] = v[a][0] * w[a][0] + v[a][1] * w[a][1] + v[a][2] * w[a][2];
        ctxs[a][t]      = qs[a][t];
        ctxs[a][NB + t] = vn;
    }
    __syncthreads();

    const float* W1 = c1W + (size_t)it * 2 * NB * NB;
    float acc[TILE];
    float b1 = c1b[it * NB + t];
    #pragma unroll
    for (int a = 0; a < TILE; a++) acc[a] = b1;
    for (int k = 0; k < 2 * NB; k++) {
        float ww = W1[k * NB + t];
        #pragma unroll
        for (int a = 0; a < TILE; a++) acc[a] += ctxs[a][k] * ww;
    }
    #pragma unroll
    for (int a = 0; a < TILE; a++) hs[a][t] = silu_f(acc[a]);
    __syncthreads();

    const float* W2 = c2W + (size_t)it * NB * 3 * NB;
    float aq[TILE], am[TILE], aqm[TILE];
    float b20 = c2b[it * 3 * NB + t];
    float b21 = c2b[it * 3 * NB + NB + t];
    float b22 = c2b[it * 3 * NB + 2 * NB + t];
    #pragma unroll
    for (int a = 0; a < TILE; a++) { aq[a] = b20; am[a] = b21; aqm[a] = b22; }
    for (int k = 0; k < NB; k++) {
        float w0 = W2[k * 384 + t];
        float w1 = W2[k * 384 + NB + t];
        float w2 = W2[k * 384 + 2 * NB + t];
        #pragma unroll
        for (int a = 0; a < TILE; a++) {
            float h = hs[a][k];
            aq[a] += h * w0; am[a] += h * w1; aqm[a] += h * w2;
        }
    }
    #pragma unroll
    for (int a = 0; a < TILE; a++) {
        int g = a0 + a;
        g_q[g * NB + t] = qs[a][t] + aq[a] + aqm[a] * s[a];
        #pragma unroll
        for (int d = 0; d < 3; d++)
            g_mu[g * 3 * NB + d * NB + t] = mus[a][d][t] + am[a] * w[a][d];
    }
}

// ---------------- output head ----------------
__global__ void __launch_bounds__(128) k_head(
        const float* __restrict__ o1W, const float* __restrict__ o1b,
        const float* __restrict__ o2W, const float* __restrict__ o2b,
        const float* __restrict__ o3W, const float* __restrict__ o3b,
        const int* __restrict__ idx_m, float* __restrict__ y) {
    __shared__ float qs[TILE][NB];
    __shared__ float h1[TILE][NB];
    __shared__ float h2[TILE][NB];
    int t  = threadIdx.x;
    int a0 = blockIdx.x * TILE;
    #pragma unroll
    for (int a = 0; a < TILE; a++) qs[a][t] = g_q[(a0 + a) * NB + t];
    __syncthreads();

    float acc[TILE];
    float b = o1b[t];
    #pragma unroll
    for (int a = 0; a < TILE; a++) acc[a] = b;
    for (int k = 0; k < NB; k++) {
        float w = o1W[k * NB + t];
        #pragma unroll
        for (int a = 0; a < TILE; a++) acc[a] += qs[a][k] * w;
    }
    #pragma unroll
    for (int a = 0; a < TILE; a++) h1[a][t] = silu_f(acc[a]);
    __syncthreads();

    b = o2b[t];
    #pragma unroll
    for (int a = 0; a < TILE; a++) acc[a] = b;
    for (int k = 0; k < NB; k++) {
        float w = o2W[k * NB + t];
        #pragma unroll
        for (int a = 0; a < TILE; a++) acc[a] += h1[a][k] * w;
    }
    #pragma unroll
    for (int a = 0; a < TILE; a++) h2[a][t] = silu_f(acc[a]);
    __syncthreads();

    if (t < TILE) {
        float sum = o3b[0];
        for (int k = 0; k < NB; k++) sum += h2[t][k] * o3W[k];
        atomicAdd(&y[idx_m[a0 + t]], sum);
    }
}

__global__ void k_copy_mu(float* __restrict__ out) {
    int idx = blockIdx.x * blockDim.x + threadIdx.x;
    if (idx < N_ATOMS * 3 * NB) out[idx] = g_mu[idx];
}

// ---------------- launch ----------------
extern "C" void kernel_launch(void* const* d_in, const int* in_sizes, int n_in,
                              void* d_out, int out_size) {
    const float* positions = (const float*)d_in[0];
    const float* emb  = (const float*)d_in[1];
    const float* fW   = (const float*)d_in[2];
    const float* fb   = (const float*)d_in[3];
    const float* ic1W = (const float*)d_in[4];
    const float* ic1b = (const float*)d_in[5];
    const float* ic2W = (const float*)d_in[6];
    const float* ic2b = (const float*)d_in[7];
    const float* mixW = (const float*)d_in[8];
    const float* c1W  = (const float*)d_in[9];
    const float* c1b  = (const float*)d_in[10];
    const float* c2W  = (const float*)d_in[11];
    const float* c2b  = (const float*)d_in[12];
    const float* o1W  = (const float*)d_in[13];
    const float* o1b  = (const float*)d_in[14];
    const float* o2W  = (const float*)d_in[15];
    const float* o2b  = (const float*)d_in[16];
    const float* o3W  = (const float*)d_in[17];
    const float* o3b  = (const float*)d_in[18];
    const int* z      = (const int*)d_in[19];
    const int* idx_i  = (const int*)d_in[20];
    const int* idx_j  = (const int*)d_in[21];
    const int* idx_m  = (const int*)d_in[22];
    float* out = (float*)d_out;   // layout: y[64], then mu[10000*3*128]

    k_init_edges<<<(N_EDGES + 255) / 256, 256>>>(positions, idx_i, idx_j);
    k_zero_cnt<<<(N_ATOMS + 255) / 256, 256>>>();
    k_hist<<<(N_EDGES + 255) / 256, 256>>>(idx_i);
    k_scan<<<1, 1024>>>();
    k_fill<<<(N_EDGES + 255) / 256, 256>>>(idx_i);
    k_init_atoms<<<N_ATOMS, 128>>>(emb, z, out);

    for (int it = 0; it < NI; it++) {
        k_atoms_x<<<N_ATOMS / TILE, 128>>>(ic1W, ic1b, ic2W, ic2b, it);
        k_gather<<<(N_ATOMS + AT - 1) / AT, 256>>>(idx_j, fW, fb, it);
        k_atoms_update<<<N_ATOMS / TILE, 128>>>(mixW, c1W, c1b, c2W, c2b, it);
    }

    k_head<<<N_ATOMS / TILE, 128>>>(o1W, o1b, o2W, o2b, o3W, o3b, idx_m, out);
    k_copy_mu<<<(N_ATOMS * 3 * NB + 255) / 256, 256>>>(out + BATCH);
}

// round 3
// speedup vs baseline: 1.3974x; 1.0244x over previous
#include <cuda_runtime.h>
#include <math.h>

#define N_ATOMS 10000
#define N_EDGES 150000
#define NB 128
#define NI 3
#define NF (NI * 3 * NB)     // 1152 filter cols
#define N_RBF 20
#define CUTOFF 5.0f
#define EPSV 1e-8f
#define BATCH 64
#define TILE 8
#define AT 8                 // atoms per gather block (two halves of 4)
#define EB 8                 // edges per filter-precompute block

// ---------------- device scratch (static, no allocation) ----------------
__device__ float g_q   [N_ATOMS * NB];
__device__ float g_mu  [N_ATOMS * 3 * NB];
__device__ float g_x   [N_ATOMS * 3 * NB];
__device__ float g_dq  [N_ATOMS * NB];
__device__ float g_dmu [N_ATOMS * 3 * NB];
__device__ float g_phif[N_EDGES * N_RBF];           // phi * fcut
__device__ float g_fc  [N_EDGES];
__device__ float4 g_dir4[N_EDGES];                  // dir.xyz, w unused
__device__ float g_filt[(size_t)N_EDGES * NF];      // all filters, all iterations
// CSR by destination atom (idx_i)
__device__ int   g_cnt [N_ATOMS];
__device__ int   g_ofs [N_ATOMS + 1];
__device__ int   g_cur [N_ATOMS];
__device__ int   g_csr [N_EDGES];

__device__ __forceinline__ float silu_f(float v) {
    return v / (1.0f + expf(-v));
}

// ---------------- edge geometry precompute ----------------
__global__ void k_init_edges(const float* __restrict__ pos,
                             const int* __restrict__ idx_i,
                             const int* __restrict__ idx_j) {
    int e = blockIdx.x * blockDim.x + threadIdx.x;
    if (e >= N_EDGES) return;
    int i = idx_i[e], j = idx_j[e];
    float rx = pos[j * 3 + 0] - pos[i * 3 + 0];
    float ry = pos[j * 3 + 1] - pos[i * 3 + 1];
    float rz = pos[j * 3 + 2] - pos[i * 3 + 2];
    float d  = sqrtf(rx * rx + ry * ry + rz * rz);
    float inv = 1.0f / d;
    g_dir4[e] = make_float4(rx * inv, ry * inv, rz * inv, 0.0f);
    float fc = (d < CUTOFF) ? 0.5f * (cosf(d * (float)M_PI / CUTOFF) + 1.0f) : 0.0f;
    g_fc[e] = fc;
    const float width = CUTOFF / (float)(N_RBF - 1);
    const float coeff = -0.5f / (width * width);
    #pragma unroll
    for (int r = 0; r < N_RBF; r++) {
        float dd = d - (float)r * width;
        g_phif[e * N_RBF + r] = expf(coeff * dd * dd) * fc;
    }
}

// ---------------- dense filter precompute: filt = phi_fc @ fW + fb*fc --------
__global__ void __launch_bounds__(128) k_filters(const float* __restrict__ fW,
                                                 const float* __restrict__ fb) {
    __shared__ float ps[EB][N_RBF];
    __shared__ float fcs[EB];
    int e0 = blockIdx.x * EB;
    int t  = threadIdx.x;
    for (int idx = t; idx < EB * N_RBF; idx += 128) {
        int a = idx / N_RBF, r = idx % N_RBF;
        ps[a][r] = g_phif[(size_t)(e0 + a) * N_RBF + r];
    }
    if (t < EB) fcs[t] = g_fc[e0 + t];
    __syncthreads();

    #pragma unroll 1
    for (int grp = 0; grp < NF / 128; grp++) {
        int c = grp * 128 + t;
        float wc[N_RBF];
        #pragma unroll
        for (int r = 0; r < N_RBF; r++) wc[r] = fW[r * NF + c];
        float bias = fb[c];
        #pragma unroll
        for (int a = 0; a < EB; a++) {
            float w = bias * fcs[a];
            #pragma unroll
            for (int r = 0; r < N_RBF; r++) w += ps[a][r] * wc[r];
            g_filt[(size_t)(e0 + a) * NF + c] = w;
        }
    }
}

// ---------------- CSR build ----------------
__global__ void k_zero_cnt() {
    int a = blockIdx.x * blockDim.x + threadIdx.x;
    if (a < N_ATOMS) g_cnt[a] = 0;
}
__global__ void k_hist(const int* __restrict__ idx_i) {
    int e = blockIdx.x * blockDim.x + threadIdx.x;
    if (e < N_EDGES) atomicAdd(&g_cnt[idx_i[e]], 1);
}
__global__ void __launch_bounds__(1024) k_scan() {
    __shared__ int partial[1024];
    int t = threadIdx.x;
    int base = t * 10;
    int local[10];
    int s = 0;
    #pragma unroll
    for (int k = 0; k < 10; k++) {
        int idx = base + k;
        int c = (idx < N_ATOMS) ? g_cnt[idx] : 0;
        local[k] = s;
        s += c;
    }
    partial[t] = s;
    __syncthreads();
    for (int off = 1; off < 1024; off <<= 1) {
        int v = partial[t];
        int u = (t >= off) ? partial[t - off] : 0;
        __syncthreads();
        partial[t] = v + u;
        __syncthreads();
    }
    int pre = (t > 0) ? partial[t - 1] : 0;
    #pragma unroll
    for (int k = 0; k < 10; k++) {
        int idx = base + k;
        if (idx < N_ATOMS) {
            int o = pre + local[k];
            g_ofs[idx] = o;
            g_cur[idx] = o;
        }
    }
    if (t == 1023) g_ofs[N_ATOMS] = partial[1023];
}
__global__ void k_fill(const int* __restrict__ idx_i) {
    int e = blockIdx.x * blockDim.x + threadIdx.x;
    if (e < N_EDGES) {
        int pos = atomicAdd(&g_cur[idx_i[e]], 1);
        g_csr[pos] = e;
    }
}

// ---------------- atom init: q = emb[z], mu = 0, y = 0 ----------------
__global__ void k_init_atoms(const float* __restrict__ emb,
                             const int* __restrict__ z,
                             float* __restrict__ y_out) {
    int a = blockIdx.x;
    int t = threadIdx.x;
    g_q[a * NB + t] = emb[z[a] * NB + t];
    #pragma unroll
    for (int d = 0; d < 3; d++)
        g_mu[a * 3 * NB + d * NB + t] = 0.0f;
    if (a == 0 && t < BATCH) y_out[t] = 0.0f;
}

// ---------------- per-atom input MLP: x = silu(q@W1+b1)@W2+b2 ----------------
__global__ void __launch_bounds__(128) k_atoms_x(
        const float* __restrict__ ic1W, const float* __restrict__ ic1b,
        const float* __restrict__ ic2W, const float* __restrict__ ic2b,
        int it) {
    __shared__ float qs[TILE][NB];
    __shared__ float hs[TILE][NB];
    int t  = threadIdx.x;
    int a0 = blockIdx.x * TILE;

    #pragma unroll
    for (int a = 0; a < TILE; a++)
        qs[a][t] = g_q[(a0 + a) * NB + t];
    __syncthreads();

    const float* W1 = ic1W + (size_t)it * NB * NB;
    float acc[TILE];
    float b1 = ic1b[it * NB + t];
    #pragma unroll
    for (int a = 0; a < TILE; a++) acc[a] = b1;
    for (int k = 0; k < NB; k++) {
        float w = W1[k * NB + t];
        #pragma unroll
        for (int a = 0; a < TILE; a++) acc[a] += qs[a][k] * w;
    }
    #pragma unroll
    for (int a = 0; a < TILE; a++) hs[a][t] = silu_f(acc[a]);
    __syncthreads();

    const float* W2 = ic2W + (size_t)it * NB * 3 * NB;
    float c0[TILE], c1[TILE], c2[TILE];
    float b20 = ic2b[it * 3 * NB + t];
    float b21 = ic2b[it * 3 * NB + NB + t];
    float b22 = ic2b[it * 3 * NB + 2 * NB + t];
    #pragma unroll
    for (int a = 0; a < TILE; a++) { c0[a] = b20; c1[a] = b21; c2[a] = b22; }
    for (int k = 0; k < NB; k++) {
        float w0 = W2[k * 384 + t];
        float w1 = W2[k * 384 + NB + t];
        float w2 = W2[k * 384 + 2 * NB + t];
        #pragma unroll
        for (int a = 0; a < TILE; a++) {
            float h = hs[a][k];
            c0[a] += h * w0; c1[a] += h * w1; c2[a] += h * w2;
        }
    }
    #pragma unroll
    for (int a = 0; a < TILE; a++) {
        g_x[(a0 + a) * 384 + t]          = c0[a];
        g_x[(a0 + a) * 384 + NB + t]     = c1[a];
        g_x[(a0 + a) * 384 + 2 * NB + t] = c2[a];
    }
}

// ---------------- edge gather: per destination atom, accumulate messages ----
__global__ void __launch_bounds__(256) k_gather(
        const int* __restrict__ idx_j, int it) {
    int t    = threadIdx.x & 127;   // feature
    int half = threadIdx.x >> 7;    // 0 / 1
    int abase = blockIdx.x * AT + half * (AT / 2);
    const float* filt_it = g_filt + (size_t)it * 384;

    #pragma unroll 1
    for (int a = 0; a < AT / 2; a++) {
        int i = abase + a;
        int beg = g_ofs[i], end = g_ofs[i + 1];
        float accq = 0.0f, m0 = 0.0f, m1 = 0.0f, m2 = 0.0f;
        for (int k = beg; k < end; k++) {
            int e = g_csr[k];
            int j = __ldg(idx_j + e);
            float4 d4 = g_dir4[e];
            const float* fe = filt_it + (size_t)e * NF;
            float w0 = fe[t];
            float w1 = fe[NB + t];
            float w2 = fe[2 * NB + t];
            const float* xj = g_x + (size_t)j * 384;
            float vq = w0 * xj[t];
            float vR = w1 * xj[NB + t];
            float vM = w2 * xj[2 * NB + t];
            const float* muj = g_mu + (size_t)j * 3 * NB;
            accq += vq;
            m0 += vR * d4.x + vM * muj[t];
            m1 += vR * d4.y + vM * muj[NB + t];
            m2 += vR * d4.z + vM * muj[2 * NB + t];
        }
        g_dq[i * NB + t] = accq;
        g_dmu[i * 3 * NB + t]          = m0;
        g_dmu[i * 3 * NB + NB + t]     = m1;
        g_dmu[i * 3 * NB + 2 * NB + t] = m2;
    }
}

// ---------------- per-atom update: q+=dq, mu+=dmu, mix + ctx MLP ----------------
__global__ void __launch_bounds__(128) k_atoms_update(
        const float* __restrict__ mixW,
        const float* __restrict__ c1W, const float* __restrict__ c1b,
        const float* __restrict__ c2W, const float* __restrict__ c2b,
        int it) {
    __shared__ float qs[TILE][NB];
    __shared__ float mus[TILE][3][NB];
    __shared__ float ctxs[TILE][2 * NB];
    __shared__ float hs[TILE][NB];
    int t  = threadIdx.x;
    int a0 = blockIdx.x * TILE;

    #pragma unroll
    for (int a = 0; a < TILE; a++) {
        int g = a0 + a;
        qs[a][t] = g_q[g * NB + t] + g_dq[g * NB + t];
        #pragma unroll
        for (int d = 0; d < 3; d++)
            mus[a][d][t] = g_mu[g * 3 * NB + d * NB + t] + g_dmu[g * 3 * NB + d * NB + t];
    }
    __syncthreads();

    const float* MW = mixW + (size_t)it * NB * 2 * NB;
    float v[TILE][3], w[TILE][3];
    #pragma unroll
    for (int a = 0; a < TILE; a++)
        #pragma unroll
        for (int d = 0; d < 3; d++) { v[a][d] = 0.0f; w[a][d] = 0.0f; }
    for (int k = 0; k < NB; k++) {
        float wv = MW[k * 256 + t];
        float ww = MW[k * 256 + NB + t];
        #pragma unroll
        for (int a = 0; a < TILE; a++) {
            #pragma unroll
            for (int d = 0; d < 3; d++) {
                float m = mus[a][d][k];
                v[a][d] += m * wv;
                w[a][d] += m * ww;
            }
        }
    }
    float s[TILE];
    #pragma unroll
    for (int a = 0; a < TILE; a++) {
        float n2 = v[a][0] * v[a][0] + v[a][1] * v[a][1] + v[a][2] * v[a][2];
        float vn = sqrtf(n2 + EPSV);
        s[a] = v[a][0] * w[a][0] + v[a][1] * w[a][1] + v[a][2] * w[a][2];
        ctxs[a][t]      = qs[a][t];
        ctxs[a][NB + t] = vn;
    }
    __syncthreads();

    const float* W1 = c1W + (size_t)it * 2 * NB * NB;
    float acc[TILE];
    float b1 = c1b[it * NB + t];
    #pragma unroll
    for (int a = 0; a < TILE; a++) acc[a] = b1;
    for (int k = 0; k < 2 * NB; k++) {
        float ww = W1[k * NB + t];
        #pragma unroll
        for (int a = 0; a < TILE; a++) acc[a] += ctxs[a][k] * ww;
    }
    #pragma unroll
    for (int a = 0; a < TILE; a++) hs[a][t] = silu_f(acc[a]);
    __syncthreads();

    const float* W2 = c2W + (size_t)it * NB * 3 * NB;
    float aq[TILE], am[TILE], aqm[TILE];
    float b20 = c2b[it * 3 * NB + t];
    float b21 = c2b[it * 3 * NB + NB + t];
    float b22 = c2b[it * 3 * NB + 2 * NB + t];
    #pragma unroll
    for (int a = 0; a < TILE; a++) { aq[a] = b20; am[a] = b21; aqm[a] = b22; }
    for (int k = 0; k < NB; k++) {
        float w0 = W2[k * 384 + t];
        float w1 = W2[k * 384 + NB + t];
        float w2 = W2[k * 384 + 2 * NB + t];
        #pragma unroll
        for (int a = 0; a < TILE; a++) {
            float h = hs[a][k];
            aq[a] += h * w0; am[a] += h * w1; aqm[a] += h * w2;
        }
    }
    #pragma unroll
    for (int a = 0; a < TILE; a++) {
        int g = a0 + a;
        g_q[g * NB + t] = qs[a][t] + aq[a] + aqm[a] * s[a];
        #pragma unroll
        for (int d = 0; d < 3; d++)
            g_mu[g * 3 * NB + d * NB + t] = mus[a][d][t] + am[a] * w[a][d];
    }
}

// ---------------- output head ----------------
__global__ void __launch_bounds__(128) k_head(
        const float* __restrict__ o1W, const float* __restrict__ o1b,
        const float* __restrict__ o2W, const float* __restrict__ o2b,
        const float* __restrict__ o3W, const float* __restrict__ o3b,
        const int* __restrict__ idx_m, float* __restrict__ y) {
    __shared__ float qs[TILE][NB];
    __shared__ float h1[TILE][NB];
    __shared__ float h2[TILE][NB];
    int t  = threadIdx.x;
    int a0 = blockIdx.x * TILE;
    #pragma unroll
    for (int a = 0; a < TILE; a++) qs[a][t] = g_q[(a0 + a) * NB + t];
    __syncthreads();

    float acc[TILE];
    float b = o1b[t];
    #pragma unroll
    for (int a = 0; a < TILE; a++) acc[a] = b;
    for (int k = 0; k < NB; k++) {
        float w = o1W[k * NB + t];
        #pragma unroll
        for (int a = 0; a < TILE; a++) acc[a] += qs[a][k] * w;
    }
    #pragma unroll
    for (int a = 0; a < TILE; a++) h1[a][t] = silu_f(acc[a]);
    __syncthreads();

    b = o2b[t];
    #pragma unroll
    for (int a = 0; a < TILE; a++) acc[a] = b;
    for (int k = 0; k < NB; k++) {
        float w = o2W[k * NB + t];
        #pragma unroll
        for (int a = 0; a < TILE; a++) acc[a] += h1[a][k] * w;
    }
    #pragma unroll
    for (int a = 0; a < TILE; a++) h2[a][t] = silu_f(acc[a]);
    __syncthreads();

    if (t < TILE) {
        float sum = o3b[0];
        for (int k = 0; k < NB; k++) sum += h2[t][k] * o3W[k];
        atomicAdd(&y[idx_m[a0 + t]], sum);
    }
}

__global__ void k_copy_mu(float* __restrict__ out) {
    int idx = blockIdx.x * blockDim.x + threadIdx.x;
    if (idx < N_ATOMS * 3 * NB) out[idx] = g_mu[idx];
}

// ---------------- launch ----------------
extern "C" void kernel_launch(void* const* d_in, const int* in_sizes, int n_in,
                              void* d_out, int out_size) {
    const float* positions = (const float*)d_in[0];
    const float* emb  = (const float*)d_in[1];
    const float* fW   = (const float*)d_in[2];
    const float* fb   = (const float*)d_in[3];
    const float* ic1W = (const float*)d_in[4];
    const float* ic1b = (const float*)d_in[5];
    const float* ic2W = (const float*)d_in[6];
    const float* ic2b = (const float*)d_in[7];
    const float* mixW = (const float*)d_in[8];
    const float* c1W  = (const float*)d_in[9];
    const float* c1b  = (const float*)d_in[10];
    const float* c2W  = (const float*)d_in[11];
    const float* c2b  = (const float*)d_in[12];
    const float* o1W  = (const float*)d_in[13];
    const float* o1b  = (const float*)d_in[14];
    const float* o2W  = (const float*)d_in[15];
    const float* o2b  = (const float*)d_in[16];
    const float* o3W  = (const float*)d_in[17];
    const float* o3b  = (const float*)d_in[18];
    const int* z      = (const int*)d_in[19];
    const int* idx_i  = (const int*)d_in[20];
    const int* idx_j  = (const int*)d_in[21];
    const int* idx_m  = (const int*)d_in[22];
    float* out = (float*)d_out;   // layout: y[64], then mu[10000*3*128]

    k_init_edges<<<(N_EDGES + 255) / 256, 256>>>(positions, idx_i, idx_j);
    k_filters<<<N_EDGES / EB, 128>>>(fW, fb);
    k_zero_cnt<<<(N_ATOMS + 255) / 256, 256>>>();
    k_hist<<<(N_EDGES + 255) / 256, 256>>>(idx_i);
    k_scan<<<1, 1024>>>();
    k_fill<<<(N_EDGES + 255) / 256, 256>>>(idx_i);
    k_init_atoms<<<N_ATOMS, 128>>>(emb, z, out);

    for (int it = 0; it < NI; it++) {
        k_atoms_x<<<N_ATOMS / TILE, 128>>>(ic1W, ic1b, ic2W, ic2b, it);
        k_gather<<<(N_ATOMS + AT - 1) / AT, 256>>>(idx_j, it);
        k_atoms_update<<<N_ATOMS / TILE, 128>>>(mixW, c1W, c1b, c2W, c2b, it);
    }

    k_head<<<N_ATOMS / TILE, 128>>>(o1W, o1b, o2W, o2b, o3W, o3b, idx_m, out);
    k_copy_mu<<<(N_ATOMS * 3 * NB + 255) / 256, 256>>>(out + BATCH);
}

// round 4
// speedup vs baseline: 1.5306x; 1.0953x over previous
#include <cuda_runtime.h>
#include <math.h>

#define N_ATOMS 10000
#define N_EDGES 150000
#define NB 128
#define NI 3
#define NF (NI * 3 * NB)     // 1152 filter cols
#define N_RBF 20
#define CUTOFF 5.0f
#define EPSV 1e-8f
#define BATCH 64
#define TILE 8
#define EB 8                 // edges per filter-precompute block

// ---------------- device scratch (static, no allocation) ----------------
__device__ float g_q   [N_ATOMS * NB];
__device__ float g_mu  [N_ATOMS * 3 * NB];
__device__ float g_x   [N_ATOMS * 3 * NB];
__device__ float g_dq  [N_ATOMS * NB];
__device__ float g_dmu [N_ATOMS * 3 * NB];
__device__ float g_phif[N_EDGES * N_RBF];           // phi * fcut
__device__ float g_fc  [N_EDGES];
__device__ float4 g_dir4[N_EDGES];                  // dir (edge order)
__device__ float g_filt[(size_t)N_EDGES * NF];      // filters in CSR-slot order
// CSR by destination atom (idx_i)
__device__ int    g_cnt [N_ATOMS];
__device__ int    g_ofs [N_ATOMS + 1];
__device__ int    g_cur [N_ATOMS];
__device__ int    g_slot[N_EDGES];                  // edge -> CSR slot
__device__ int    g_pj  [N_EDGES];                  // idx_j in CSR-slot order
__device__ float4 g_pdir[N_EDGES];                  // dir in CSR-slot order

__device__ __forceinline__ float silu_f(float v) {
    return v / (1.0f + expf(-v));
}
__device__ __forceinline__ float4 f4fma(float4 a, float4 b, float4 c) {
    return make_float4(fmaf(a.x,b.x,c.x), fmaf(a.y,b.y,c.y),
                       fmaf(a.z,b.z,c.z), fmaf(a.w,b.w,c.w));
}
__device__ __forceinline__ float4 f4fmas(float4 a, float s, float4 c) {
    return make_float4(fmaf(a.x,s,c.x), fmaf(a.y,s,c.y),
                       fmaf(a.z,s,c.z), fmaf(a.w,s,c.w));
}

// ---------------- edge geometry precompute ----------------
__global__ void k_init_edges(const float* __restrict__ pos,
                             const int* __restrict__ idx_i,
                             const int* __restrict__ idx_j) {
    int e = blockIdx.x * blockDim.x + threadIdx.x;
    if (e >= N_EDGES) return;
    int i = idx_i[e], j = idx_j[e];
    float rx = pos[j * 3 + 0] - pos[i * 3 + 0];
    float ry = pos[j * 3 + 1] - pos[i * 3 + 1];
    float rz = pos[j * 3 + 2] - pos[i * 3 + 2];
    float d  = sqrtf(rx * rx + ry * ry + rz * rz);
    float inv = 1.0f / d;
    g_dir4[e] = make_float4(rx * inv, ry * inv, rz * inv, 0.0f);
    float fc = (d < CUTOFF) ? 0.5f * (cosf(d * (float)M_PI / CUTOFF) + 1.0f) : 0.0f;
    g_fc[e] = fc;
    const float width = CUTOFF / (float)(N_RBF - 1);
    const float coeff = -0.5f / (width * width);
    #pragma unroll
    for (int r = 0; r < N_RBF; r++) {
        float dd = d - (float)r * width;
        g_phif[e * N_RBF + r] = expf(coeff * dd * dd) * fc;
    }
}

// ---------------- CSR build ----------------
__global__ void k_zero_cnt() {
    int a = blockIdx.x * blockDim.x + threadIdx.x;
    if (a < N_ATOMS) g_cnt[a] = 0;
}
__global__ void k_hist(const int* __restrict__ idx_i) {
    int e = blockIdx.x * blockDim.x + threadIdx.x;
    if (e < N_EDGES) atomicAdd(&g_cnt[idx_i[e]], 1);
}
__global__ void __launch_bounds__(1024) k_scan() {
    __shared__ int partial[1024];
    int t = threadIdx.x;
    int base = t * 10;
    int local[10];
    int s = 0;
    #pragma unroll
    for (int k = 0; k < 10; k++) {
        int idx = base + k;
        int c = (idx < N_ATOMS) ? g_cnt[idx] : 0;
        local[k] = s;
        s += c;
    }
    partial[t] = s;
    __syncthreads();
    for (int off = 1; off < 1024; off <<= 1) {
        int v = partial[t];
        int u = (t >= off) ? partial[t - off] : 0;
        __syncthreads();
        partial[t] = v + u;
        __syncthreads();
    }
    int pre = (t > 0) ? partial[t - 1] : 0;
    #pragma unroll
    for (int k = 0; k < 10; k++) {
        int idx = base + k;
        if (idx < N_ATOMS) {
            int o = pre + local[k];
            g_ofs[idx] = o;
            g_cur[idx] = o;
        }
    }
    if (t == 1023) g_ofs[N_ATOMS] = partial[1023];
}
// fill: record slot, and write permuted idx_j / dir
__global__ void k_fill(const int* __restrict__ idx_i,
                       const int* __restrict__ idx_j) {
    int e = blockIdx.x * blockDim.x + threadIdx.x;
    if (e < N_EDGES) {
        int pos = atomicAdd(&g_cur[idx_i[e]], 1);
        g_slot[e] = pos;
        g_pj[pos] = idx_j[e];
        g_pdir[pos] = g_dir4[e];
    }
}

// ---------------- dense filter precompute into CSR-slot rows ----------------
__global__ void __launch_bounds__(128) k_filters(const float* __restrict__ fW,
                                                 const float* __restrict__ fb) {
    __shared__ float ps[EB][N_RBF];
    __shared__ float fcs[EB];
    __shared__ int   slots[EB];
    int e0 = blockIdx.x * EB;
    int t  = threadIdx.x;
    for (int idx = t; idx < EB * N_RBF; idx += 128) {
        int a = idx / N_RBF, r = idx % N_RBF;
        ps[a][r] = g_phif[(size_t)(e0 + a) * N_RBF + r];
    }
    if (t < EB) {
        fcs[t] = g_fc[e0 + t];
        slots[t] = g_slot[e0 + t];
    }
    __syncthreads();

    #pragma unroll 1
    for (int grp = 0; grp < NF / 128; grp++) {
        int c = grp * 128 + t;
        float wc[N_RBF];
        #pragma unroll
        for (int r = 0; r < N_RBF; r++) wc[r] = fW[r * NF + c];
        float bias = fb[c];
        #pragma unroll
        for (int a = 0; a < EB; a++) {
            float w = bias * fcs[a];
            #pragma unroll
            for (int r = 0; r < N_RBF; r++) w += ps[a][r] * wc[r];
            g_filt[(size_t)slots[a] * NF + c] = w;
        }
    }
}

// ---------------- atom init ----------------
__global__ void k_init_atoms(const float* __restrict__ emb,
                             const int* __restrict__ z,
                             float* __restrict__ y_out) {
    int a = blockIdx.x;
    int t = threadIdx.x;
    g_q[a * NB + t] = emb[z[a] * NB + t];
    #pragma unroll
    for (int d = 0; d < 3; d++)
        g_mu[a * 3 * NB + d * NB + t] = 0.0f;
    if (a == 0 && t < BATCH) y_out[t] = 0.0f;
}

// ---------------- per-atom input MLP ----------------
__global__ void __launch_bounds__(128) k_atoms_x(
        const float* __restrict__ ic1W, const float* __restrict__ ic1b,
        const float* __restrict__ ic2W, const float* __restrict__ ic2b,
        int it) {
    __shared__ float qs[TILE][NB];
    __shared__ float hs[TILE][NB];
    int t  = threadIdx.x;
    int a0 = blockIdx.x * TILE;

    #pragma unroll
    for (int a = 0; a < TILE; a++)
        qs[a][t] = g_q[(a0 + a) * NB + t];
    __syncthreads();

    const float* W1 = ic1W + (size_t)it * NB * NB;
    float acc[TILE];
    float b1 = ic1b[it * NB + t];
    #pragma unroll
    for (int a = 0; a < TILE; a++) acc[a] = b1;
    for (int k = 0; k < NB; k++) {
        float w = W1[k * NB + t];
        #pragma unroll
        for (int a = 0; a < TILE; a++) acc[a] += qs[a][k] * w;
    }
    #pragma unroll
    for (int a = 0; a < TILE; a++) hs[a][t] = silu_f(acc[a]);
    __syncthreads();

    const float* W2 = ic2W + (size_t)it * NB * 3 * NB;
    float c0[TILE], c1[TILE], c2[TILE];
    float b20 = ic2b[it * 3 * NB + t];
    float b21 = ic2b[it * 3 * NB + NB + t];
    float b22 = ic2b[it * 3 * NB + 2 * NB + t];
    #pragma unroll
    for (int a = 0; a < TILE; a++) { c0[a] = b20; c1[a] = b21; c2[a] = b22; }
    for (int k = 0; k < NB; k++) {
        float w0 = W2[k * 384 + t];
        float w1 = W2[k * 384 + NB + t];
        float w2 = W2[k * 384 + 2 * NB + t];
        #pragma unroll
        for (int a = 0; a < TILE; a++) {
            float h = hs[a][k];
            c0[a] += h * w0; c1[a] += h * w1; c2[a] += h * w2;
        }
    }
    #pragma unroll
    for (int a = 0; a < TILE; a++) {
        g_x[(a0 + a) * 384 + t]          = c0[a];
        g_x[(a0 + a) * 384 + NB + t]     = c1[a];
        g_x[(a0 + a) * 384 + 2 * NB + t] = c2[a];
    }
}

// ---------------- edge gather: one warp per destination atom, float4 lanes ----
__global__ void __launch_bounds__(256) k_gather(int it) {
    int warp = threadIdx.x >> 5;
    int lane = threadIdx.x & 31;
    int i = blockIdx.x * 8 + warp;
    int beg = g_ofs[i], end = g_ofs[i + 1];

    float4 accq = make_float4(0,0,0,0);
    float4 m0 = accq, m1 = accq, m2 = accq;

    const size_t itofs = (size_t)it * 384;
    for (int k = beg; k < end; k++) {
        int j = __ldg(g_pj + k);
        float4 d4 = g_pdir[k];
        const float4* fe = (const float4*)(g_filt + (size_t)k * NF + itofs);
        float4 w0 = fe[lane];
        float4 w1 = fe[32 + lane];
        float4 w2 = fe[64 + lane];
        const float4* xj = (const float4*)(g_x + (size_t)j * 384);
        float4 x0 = xj[lane];
        float4 x1 = xj[32 + lane];
        float4 x2 = xj[64 + lane];
        const float4* muj = (const float4*)(g_mu + (size_t)j * 384);
        float4 u0 = muj[lane];
        float4 u1 = muj[32 + lane];
        float4 u2 = muj[64 + lane];

        accq = f4fma(w0, x0, accq);
        float4 vR = make_float4(w1.x*x1.x, w1.y*x1.y, w1.z*x1.z, w1.w*x1.w);
        float4 vM = make_float4(w2.x*x2.x, w2.y*x2.y, w2.z*x2.z, w2.w*x2.w);
        m0 = f4fmas(vR, d4.x, f4fma(vM, u0, m0));
        m1 = f4fmas(vR, d4.y, f4fma(vM, u1, m1));
        m2 = f4fmas(vR, d4.z, f4fma(vM, u2, m2));
    }
    ((float4*)(g_dq + (size_t)i * NB))[lane] = accq;
    float4* dmu = (float4*)(g_dmu + (size_t)i * 3 * NB);
    dmu[lane]      = m0;
    dmu[32 + lane] = m1;
    dmu[64 + lane] = m2;
}

// ---------------- per-atom update ----------------
__global__ void __launch_bounds__(128) k_atoms_update(
        const float* __restrict__ mixW,
        const float* __restrict__ c1W, const float* __restrict__ c1b,
        const float* __restrict__ c2W, const float* __restrict__ c2b,
        int it) {
    __shared__ float qs[TILE][NB];
    __shared__ float mus[TILE][3][NB];
    __shared__ float ctxs[TILE][2 * NB];
    __shared__ float hs[TILE][NB];
    int t  = threadIdx.x;
    int a0 = blockIdx.x * TILE;

    #pragma unroll
    for (int a = 0; a < TILE; a++) {
        int g = a0 + a;
        qs[a][t] = g_q[g * NB + t] + g_dq[g * NB + t];
        #pragma unroll
        for (int d = 0; d < 3; d++)
            mus[a][d][t] = g_mu[g * 3 * NB + d * NB + t] + g_dmu[g * 3 * NB + d * NB + t];
    }
    __syncthreads();

    const float* MW = mixW + (size_t)it * NB * 2 * NB;
    float v[TILE][3], w[TILE][3];
    #pragma unroll
    for (int a = 0; a < TILE; a++)
        #pragma unroll
        for (int d = 0; d < 3; d++) { v[a][d] = 0.0f; w[a][d] = 0.0f; }
    for (int k = 0; k < NB; k++) {
        float wv = MW[k * 256 + t];
        float ww = MW[k * 256 + NB + t];
        #pragma unroll
        for (int a = 0; a < TILE; a++) {
            #pragma unroll
            for (int d = 0; d < 3; d++) {
                float m = mus[a][d][k];
                v[a][d] += m * wv;
                w[a][d] += m * ww;
            }
        }
    }
    float s[TILE];
    #pragma unroll
    for (int a = 0; a < TILE; a++) {
        float n2 = v[a][0] * v[a][0] + v[a][1] * v[a][1] + v[a][2] * v[a][2];
        float vn = sqrtf(n2 + EPSV);
        s[a] = v[a][0] * w[a][0] + v[a][1] * w[a][1] + v[a][2] * w[a][2];
        ctxs[a][t]      = qs[a][t];
        ctxs[a][NB + t] = vn;
    }
    __syncthreads();

    const float* W1 = c1W + (size_t)it * 2 * NB * NB;
    float acc[TILE];
    float b1 = c1b[it * NB + t];
    #pragma unroll
    for (int a = 0; a < TILE; a++) acc[a] = b1;
    for (int k = 0; k < 2 * NB; k++) {
        float ww = W1[k * NB + t];
        #pragma unroll
        for (int a = 0; a < TILE; a++) acc[a] += ctxs[a][k] * ww;
    }
    #pragma unroll
    for (int a = 0; a < TILE; a++) hs[a][t] = silu_f(acc[a]);
    __syncthreads();

    const float* W2 = c2W + (size_t)it * NB * 3 * NB;
    float aq[TILE], am[TILE], aqm[TILE];
    float b20 = c2b[it * 3 * NB + t];
    float b21 = c2b[it * 3 * NB + NB + t];
    float b22 = c2b[it * 3 * NB + 2 * NB + t];
    #pragma unroll
    for (int a = 0; a < TILE; a++) { aq[a] = b20; am[a] = b21; aqm[a] = b22; }
    for (int k = 0; k < NB; k++) {
        float w0 = W2[k * 384 + t];
        float w1 = W2[k * 384 + NB + t];
        float w2 = W2[k * 384 + 2 * NB + t];
        #pragma unroll
        for (int a = 0; a < TILE; a++) {
            float h = hs[a][k];
            aq[a] += h * w0; am[a] += h * w1; aqm[a] += h * w2;
        }
    }
    #pragma unroll
    for (int a = 0; a < TILE; a++) {
        int g = a0 + a;
        g_q[g * NB + t] = qs[a][t] + aq[a] + aqm[a] * s[a];
        #pragma unroll
        for (int d = 0; d < 3; d++)
            g_mu[g * 3 * NB + d * NB + t] = mus[a][d][t] + am[a] * w[a][d];
    }
}

// ---------------- output head ----------------
__global__ void __launch_bounds__(128) k_head(
        const float* __restrict__ o1W, const float* __restrict__ o1b,
        const float* __restrict__ o2W, const float* __restrict__ o2b,
        const float* __restrict__ o3W, const float* __restrict__ o3b,
        const int* __restrict__ idx_m, float* __restrict__ y) {
    __shared__ float qs[TILE][NB];
    __shared__ float h1[TILE][NB];
    __shared__ float h2[TILE][NB];
    int t  = threadIdx.x;
    int a0 = blockIdx.x * TILE;
    #pragma unroll
    for (int a = 0; a < TILE; a++) qs[a][t] = g_q[(a0 + a) * NB + t];
    __syncthreads();

    float acc[TILE];
    float b = o1b[t];
    #pragma unroll
    for (int a = 0; a < TILE; a++) acc[a] = b;
    for (int k = 0; k < NB; k++) {
        float w = o1W[k * NB + t];
        #pragma unroll
        for (int a = 0; a < TILE; a++) acc[a] += qs[a][k] * w;
    }
    #pragma unroll
    for (int a = 0; a < TILE; a++) h1[a][t] = silu_f(acc[a]);
    __syncthreads();

    b = o2b[t];
    #pragma unroll
    for (int a = 0; a < TILE; a++) acc[a] = b;
    for (int k = 0; k < NB; k++) {
        float w = o2W[k * NB + t];
        #pragma unroll
        for (int a = 0; a < TILE; a++) acc[a] += h1[a][k] * w;
    }
    #pragma unroll
    for (int a = 0; a < TILE; a++) h2[a][t] = silu_f(acc[a]);
    __syncthreads();

    if (t < TILE) {
        float sum = o3b[0];
        for (int k = 0; k < NB; k++) sum += h2[t][k] * o3W[k];
        atomicAdd(&y[idx_m[a0 + t]], sum);
    }
}

__global__ void k_copy_mu(float* __restrict__ out) {
    int idx = blockIdx.x * blockDim.x + threadIdx.x;
    if (idx < N_ATOMS * 3 * NB) out[idx] = g_mu[idx];
}

// ---------------- launch ----------------
extern "C" void kernel_launch(void* const* d_in, const int* in_sizes, int n_in,
                              void* d_out, int out_size) {
    const float* positions = (const float*)d_in[0];
    const float* emb  = (const float*)d_in[1];
    const float* fW   = (const float*)d_in[2];
    const float* fb   = (const float*)d_in[3];
    const float* ic1W = (const float*)d_in[4];
    const float* ic1b = (const float*)d_in[5];
    const float* ic2W = (const float*)d_in[6];
    const float* ic2b = (const float*)d_in[7];
    const float* mixW = (const float*)d_in[8];
    const float* c1W  = (const float*)d_in[9];
    const float* c1b  = (const float*)d_in[10];
    const float* c2W  = (const float*)d_in[11];
    const float* c2b  = (const float*)d_in[12];
    const float* o1W  = (const float*)d_in[13];
    const float* o1b  = (const float*)d_in[14];
    const float* o2W  = (const float*)d_in[15];
    const float* o2b  = (const float*)d_in[16];
    const float* o3W  = (const float*)d_in[17];
    const float* o3b  = (const float*)d_in[18];
    const int* z      = (const int*)d_in[19];
    const int* idx_i  = (const int*)d_in[20];
    const int* idx_j  = (const int*)d_in[21];
    const int* idx_m  = (const int*)d_in[22];
    float* out = (float*)d_out;   // layout: y[64], then mu[10000*3*128]

    k_init_edges<<<(N_EDGES + 255) / 256, 256>>>(positions, idx_i, idx_j);
    k_zero_cnt<<<(N_ATOMS + 255) / 256, 256>>>();
    k_hist<<<(N_EDGES + 255) / 256, 256>>>(idx_i);
    k_scan<<<1, 1024>>>();
    k_fill<<<(N_EDGES + 255) / 256, 256>>>(idx_i, idx_j);
    k_filters<<<N_EDGES / EB, 128>>>(fW, fb);
    k_init_atoms<<<N_ATOMS, 128>>>(emb, z, out);

    for (int it = 0; it < NI; it++) {
        k_atoms_x<<<N_ATOMS / TILE, 128>>>(ic1W, ic1b, ic2W, ic2b, it);
        k_gather<<<N_ATOMS / 8, 256>>>(it);
        k_atoms_update<<<N_ATOMS / TILE, 128>>>(mixW, c1W, c1b, c2W, c2b, it);
    }

    k_head<<<N_ATOMS / TILE, 128>>>(o1W, o1b, o2W, o2b, o3W, o3b, idx_m, out);
    k_copy_mu<<<(N_ATOMS * 3 * NB + 255) / 256, 256>>>(out + BATCH);
}

// round 5
// speedup vs baseline: 1.8599x; 1.2152x over previous
#include <cuda_runtime.h>
#include <cuda_fp16.h>
#include <math.h>

#define N_ATOMS 10000
#define N_EDGES 150000
#define NB 128
#define NI 3
#define NF (NI * 3 * NB)     // 1152 filter cols
#define N_RBF 20
#define CUTOFF 5.0f
#define EPSV 1e-8f
#define BATCH 64
#define EB 8                 // edges per filter-precompute block
#define TX 16                // atoms per block, k_atoms_x
#define PX 20                // padded row for TX
#define TU 8                 // atoms per block, k_atoms_update
#define PU 12                // padded row for TU
#define TH 8                 // atoms per block, k_head

// ---------------- device scratch (static, no allocation) ----------------
__device__ float  g_q   [N_ATOMS * NB];
__device__ float  g_mu  [N_ATOMS * 3 * NB];
__device__ float  g_x   [N_ATOMS * 3 * NB];
__device__ float  g_dq  [N_ATOMS * NB];
__device__ float  g_dmu [N_ATOMS * 3 * NB];
__device__ float  g_phif[N_EDGES * N_RBF];
__device__ float  g_fc  [N_EDGES];
__device__ float4 g_dir4[N_EDGES];
__device__ __half g_filt[(size_t)N_EDGES * NF];     // filters (fp16) in CSR-slot order
// CSR by destination atom (idx_i)
__device__ int    g_cnt [N_ATOMS];
__device__ int    g_ofs [N_ATOMS + 1];
__device__ int    g_cur [N_ATOMS];
__device__ int    g_slot[N_EDGES];
__device__ int    g_pj  [N_EDGES];
__device__ float4 g_pdir[N_EDGES];

__device__ __forceinline__ float silu_f(float v) {
    return v / (1.0f + expf(-v));
}
__device__ __forceinline__ float4 f4fma(float4 a, float4 b, float4 c) {
    return make_float4(fmaf(a.x,b.x,c.x), fmaf(a.y,b.y,c.y),
                       fmaf(a.z,b.z,c.z), fmaf(a.w,b.w,c.w));
}
__device__ __forceinline__ float4 f4fmas(float4 a, float s, float4 c) {
    return make_float4(fmaf(a.x,s,c.x), fmaf(a.y,s,c.y),
                       fmaf(a.z,s,c.z), fmaf(a.w,s,c.w));
}
// load 4 consecutive halfs (8B aligned) as float4
__device__ __forceinline__ float4 ld_half4(const __half* base, int idx4) {
    uint2 u = ((const uint2*)base)[idx4];
    __half2 a = *reinterpret_cast<__half2*>(&u.x);
    __half2 b = *reinterpret_cast<__half2*>(&u.y);
    float2 fa = __half22float2(a);
    float2 fb = __half22float2(b);
    return make_float4(fa.x, fa.y, fb.x, fb.y);
}

// ---------------- edge geometry precompute ----------------
__global__ void k_init_edges(const float* __restrict__ pos,
                             const int* __restrict__ idx_i,
                             const int* __restrict__ idx_j) {
    int e = blockIdx.x * blockDim.x + threadIdx.x;
    if (e >= N_EDGES) return;
    int i = idx_i[e], j = idx_j[e];
    float rx = pos[j * 3 + 0] - pos[i * 3 + 0];
    float ry = pos[j * 3 + 1] - pos[i * 3 + 1];
    float rz = pos[j * 3 + 2] - pos[i * 3 + 2];
    float d  = sqrtf(rx * rx + ry * ry + rz * rz);
    float inv = 1.0f / d;
    g_dir4[e] = make_float4(rx * inv, ry * inv, rz * inv, 0.0f);
    float fc = (d < CUTOFF) ? 0.5f * (cosf(d * (float)M_PI / CUTOFF) + 1.0f) : 0.0f;
    g_fc[e] = fc;
    const float width = CUTOFF / (float)(N_RBF - 1);
    const float coeff = -0.5f / (width * width);
    #pragma unroll
    for (int r = 0; r < N_RBF; r++) {
        float dd = d - (float)r * width;
        g_phif[e * N_RBF + r] = expf(coeff * dd * dd) * fc;
    }
}

// ---------------- CSR build ----------------
__global__ void k_zero_cnt() {
    int a = blockIdx.x * blockDim.x + threadIdx.x;
    if (a < N_ATOMS) g_cnt[a] = 0;
}
__global__ void k_hist(const int* __restrict__ idx_i) {
    int e = blockIdx.x * blockDim.x + threadIdx.x;
    if (e < N_EDGES) atomicAdd(&g_cnt[idx_i[e]], 1);
}
__global__ void __launch_bounds__(1024) k_scan() {
    __shared__ int partial[1024];
    int t = threadIdx.x;
    int base = t * 10;
    int local[10];
    int s = 0;
    #pragma unroll
    for (int k = 0; k < 10; k++) {
        int idx = base + k;
        int c = (idx < N_ATOMS) ? g_cnt[idx] : 0;
        local[k] = s;
        s += c;
    }
    partial[t] = s;
    __syncthreads();
    for (int off = 1; off < 1024; off <<= 1) {
        int v = partial[t];
        int u = (t >= off) ? partial[t - off] : 0;
        __syncthreads();
        partial[t] = v + u;
        __syncthreads();
    }
    int pre = (t > 0) ? partial[t - 1] : 0;
    #pragma unroll
    for (int k = 0; k < 10; k++) {
        int idx = base + k;
        if (idx < N_ATOMS) {
            int o = pre + local[k];
            g_ofs[idx] = o;
            g_cur[idx] = o;
        }
    }
    if (t == 1023) g_ofs[N_ATOMS] = partial[1023];
}
__global__ void k_fill(const int* __restrict__ idx_i,
                       const int* __restrict__ idx_j) {
    int e = blockIdx.x * blockDim.x + threadIdx.x;
    if (e < N_EDGES) {
        int pos = atomicAdd(&g_cur[idx_i[e]], 1);
        g_slot[e] = pos;
        g_pj[pos] = idx_j[e];
        g_pdir[pos] = g_dir4[e];
    }
}

// ---------------- dense filter precompute into CSR-slot rows (fp16) ----------
__global__ void __launch_bounds__(128) k_filters(const float* __restrict__ fW,
                                                 const float* __restrict__ fb) {
    __shared__ float ps[EB][N_RBF];
    __shared__ float fcs[EB];
    __shared__ int   slots[EB];
    int e0 = blockIdx.x * EB;
    int t  = threadIdx.x;
    for (int idx = t; idx < EB * N_RBF; idx += 128) {
        int a = idx / N_RBF, r = idx % N_RBF;
        ps[a][r] = g_phif[(size_t)(e0 + a) * N_RBF + r];
    }
    if (t < EB) {
        fcs[t] = g_fc[e0 + t];
        slots[t] = g_slot[e0 + t];
    }
    __syncthreads();

    #pragma unroll 1
    for (int grp = 0; grp < NF / 128; grp++) {
        int c = grp * 128 + t;
        float wc[N_RBF];
        #pragma unroll
        for (int r = 0; r < N_RBF; r++) wc[r] = fW[r * NF + c];
        float bias = fb[c];
        #pragma unroll
        for (int a = 0; a < EB; a++) {
            float w = bias * fcs[a];
            #pragma unroll
            for (int r = 0; r < N_RBF; r++) w += ps[a][r] * wc[r];
            g_filt[(size_t)slots[a] * NF + c] = __float2half_rn(w);
        }
    }
}

// ---------------- atom init ----------------
__global__ void k_init_atoms(const float* __restrict__ emb,
                             const int* __restrict__ z,
                             float* __restrict__ y_out) {
    int a = blockIdx.x;
    int t = threadIdx.x;
    g_q[a * NB + t] = emb[z[a] * NB + t];
    #pragma unroll
    for (int d = 0; d < 3; d++)
        g_mu[a * 3 * NB + d * NB + t] = 0.0f;
    if (a == 0 && t < BATCH) y_out[t] = 0.0f;
}

// ---------------- per-atom input MLP (transposed smem, TX atoms) ------------
__global__ void __launch_bounds__(128) k_atoms_x(
        const float* __restrict__ ic1W, const float* __restrict__ ic1b,
        const float* __restrict__ ic2W, const float* __restrict__ ic2b,
        int it) {
    __shared__ __align__(16) float qs[NB][PX];
    __shared__ __align__(16) float hs[NB][PX];
    int t  = threadIdx.x;
    int a0 = blockIdx.x * TX;

    #pragma unroll
    for (int a = 0; a < TX; a++)
        qs[t][a] = g_q[(size_t)(a0 + a) * NB + t];
    __syncthreads();

    const float* W1 = ic1W + (size_t)it * NB * NB;
    float acc[TX];
    float b1 = ic1b[it * NB + t];
    #pragma unroll
    for (int a = 0; a < TX; a++) acc[a] = b1;
    for (int k = 0; k < NB; k++) {
        float w = W1[k * NB + t];
        float4 q0 = *(const float4*)&qs[k][0];
        float4 q1 = *(const float4*)&qs[k][4];
        float4 q2 = *(const float4*)&qs[k][8];
        float4 q3 = *(const float4*)&qs[k][12];
        float qa[TX] = {q0.x,q0.y,q0.z,q0.w, q1.x,q1.y,q1.z,q1.w,
                        q2.x,q2.y,q2.z,q2.w, q3.x,q3.y,q3.z,q3.w};
        #pragma unroll
        for (int a = 0; a < TX; a++) acc[a] = fmaf(qa[a], w, acc[a]);
    }
    #pragma unroll
    for (int a = 0; a < TX; a++) hs[t][a] = silu_f(acc[a]);
    __syncthreads();

    const float* W2 = ic2W + (size_t)it * NB * 3 * NB;
    float c0[TX], c1[TX], c2[TX];
    float b20 = ic2b[it * 3 * NB + t];
    float b21 = ic2b[it * 3 * NB + NB + t];
    float b22 = ic2b[it * 3 * NB + 2 * NB + t];
    #pragma unroll
    for (int a = 0; a < TX; a++) { c0[a] = b20; c1[a] = b21; c2[a] = b22; }
    for (int k = 0; k < NB; k++) {
        float w0 = W2[k * 384 + t];
        float w1 = W2[k * 384 + NB + t];
        float w2 = W2[k * 384 + 2 * NB + t];
        float4 h0 = *(const float4*)&hs[k][0];
        float4 h1 = *(const float4*)&hs[k][4];
        float4 h2 = *(const float4*)&hs[k][8];
        float4 h3 = *(const float4*)&hs[k][12];
        float ha[TX] = {h0.x,h0.y,h0.z,h0.w, h1.x,h1.y,h1.z,h1.w,
                        h2.x,h2.y,h2.z,h2.w, h3.x,h3.y,h3.z,h3.w};
        #pragma unroll
        for (int a = 0; a < TX; a++) {
            c0[a] = fmaf(ha[a], w0, c0[a]);
            c1[a] = fmaf(ha[a], w1, c1[a]);
            c2[a] = fmaf(ha[a], w2, c2[a]);
        }
    }
    #pragma unroll
    for (int a = 0; a < TX; a++) {
        size_t g = (size_t)(a0 + a) * 384;
        g_x[g + t]          = c0[a];
        g_x[g + NB + t]     = c1[a];
        g_x[g + 2 * NB + t] = c2[a];
    }
}

// ---------------- edge gather: one warp per destination atom, float4 lanes ----
__global__ void __launch_bounds__(256) k_gather(int it) {
    int warp = threadIdx.x >> 5;
    int lane = threadIdx.x & 31;
    int i = blockIdx.x * 8 + warp;
    int beg = g_ofs[i], end = g_ofs[i + 1];

    float4 accq = make_float4(0,0,0,0);
    float4 m0 = accq, m1 = accq, m2 = accq;

    const int itofs = it * 384;   // in half units
    for (int k = beg; k < end; k++) {
        int j = __ldg(g_pj + k);
        float4 d4 = g_pdir[k];
        const __half* fe = g_filt + (size_t)k * NF + itofs;
        float4 w0 = ld_half4(fe, lane);
        float4 w1 = ld_half4(fe, 32 + lane);
        float4 w2 = ld_half4(fe, 64 + lane);
        const float4* xj = (const float4*)(g_x + (size_t)j * 384);
        float4 x0 = xj[lane];
        float4 x1 = xj[32 + lane];
        float4 x2 = xj[64 + lane];
        const float4* muj = (const float4*)(g_mu + (size_t)j * 384);
        float4 u0 = muj[lane];
        float4 u1 = muj[32 + lane];
        float4 u2 = muj[64 + lane];

        accq = f4fma(w0, x0, accq);
        float4 vR = make_float4(w1.x*x1.x, w1.y*x1.y, w1.z*x1.z, w1.w*x1.w);
        float4 vM = make_float4(w2.x*x2.x, w2.y*x2.y, w2.z*x2.z, w2.w*x2.w);
        m0 = f4fmas(vR, d4.x, f4fma(vM, u0, m0));
        m1 = f4fmas(vR, d4.y, f4fma(vM, u1, m1));
        m2 = f4fmas(vR, d4.z, f4fma(vM, u2, m2));
    }
    ((float4*)(g_dq + (size_t)i * NB))[lane] = accq;
    float4* dmu = (float4*)(g_dmu + (size_t)i * 3 * NB);
    dmu[lane]      = m0;
    dmu[32 + lane] = m1;
    dmu[64 + lane] = m2;
}

// ---------------- per-atom update (transposed smem, TU atoms) ---------------
__global__ void __launch_bounds__(128) k_atoms_update(
        const float* __restrict__ mixW,
        const float* __restrict__ c1W, const float* __restrict__ c1b,
        const float* __restrict__ c2W, const float* __restrict__ c2b,
        int it, int last, float* __restrict__ mu_out) {
    __shared__ __align__(16) float mus[NB][3][PU];     // [k][d][a]
    __shared__ __align__(16) float ctxs[2 * NB][PU];   // [k][a]
    __shared__ __align__(16) float hs[NB][PU];         // [k][a]
    int t  = threadIdx.x;
    int a0 = blockIdx.x * TU;

    float qreg[TU];
    #pragma unroll
    for (int a = 0; a < TU; a++) {
        size_t g = (size_t)(a0 + a);
        qreg[a] = g_q[g * NB + t] + g_dq[g * NB + t];
        ctxs[t][a] = qreg[a];
        #pragma unroll
        for (int d = 0; d < 3; d++)
            mus[t][d][a] = g_mu[g * 3 * NB + d * NB + t] + g_dmu[g * 3 * NB + d * NB + t];
    }
    __syncthreads();

    const float* MW = mixW + (size_t)it * NB * 2 * NB;
    float v[TU][3], w[TU][3];
    #pragma unroll
    for (int a = 0; a < TU; a++)
        #pragma unroll
        for (int d = 0; d < 3; d++) { v[a][d] = 0.0f; w[a][d] = 0.0f; }
    for (int k = 0; k < NB; k++) {
        float wv = MW[k * 256 + t];
        float ww = MW[k * 256 + NB + t];
        #pragma unroll
        for (int d = 0; d < 3; d++) {
            float4 mA = *(const float4*)&mus[k][d][0];
            float4 mB = *(const float4*)&mus[k][d][4];
            float ma[TU] = {mA.x,mA.y,mA.z,mA.w, mB.x,mB.y,mB.z,mB.w};
            #pragma unroll
            for (int a = 0; a < TU; a++) {
                v[a][d] = fmaf(ma[a], wv, v[a][d]);
                w[a][d] = fmaf(ma[a], ww, w[a][d]);
            }
        }
    }
    float s[TU];
    #pragma unroll
    for (int a = 0; a < TU; a++) {
        float n2 = v[a][0]*v[a][0] + v[a][1]*v[a][1] + v[a][2]*v[a][2];
        float vn = sqrtf(n2 + EPSV);
        s[a] = v[a][0]*w[a][0] + v[a][1]*w[a][1] + v[a][2]*w[a][2];
        ctxs[NB + t][a] = vn;
    }
    __syncthreads();

    const float* W1 = c1W + (size_t)it * 2 * NB * NB;
    float acc[TU];
    float b1 = c1b[it * NB + t];
    #pragma unroll
    for (int a = 0; a < TU; a++) acc[a] = b1;
    for (int k = 0; k < 2 * NB; k++) {
        float ww1 = W1[k * NB + t];
        float4 cA = *(const float4*)&ctxs[k][0];
        float4 cB = *(const float4*)&ctxs[k][4];
        float ca[TU] = {cA.x,cA.y,cA.z,cA.w, cB.x,cB.y,cB.z,cB.w};
        #pragma unroll
        for (int a = 0; a < TU; a++) acc[a] = fmaf(ca[a], ww1, acc[a]);
    }
    #pragma unroll
    for (int a = 0; a < TU; a++) hs[t][a] = silu_f(acc[a]);
    __syncthreads();

    const float* W2 = c2W + (size_t)it * NB * 3 * NB;
    float aq[TU], am[TU], aqm[TU];
    float b20 = c2b[it * 3 * NB + t];
    float b21 = c2b[it * 3 * NB + NB + t];
    float b22 = c2b[it * 3 * NB + 2 * NB + t];
    #pragma unroll
    for (int a = 0; a < TU; a++) { aq[a] = b20; am[a] = b21; aqm[a] = b22; }
    for (int k = 0; k < NB; k++) {
        float w0 = W2[k * 384 + t];
        float w1 = W2[k * 384 + NB + t];
        float w2 = W2[k * 384 + 2 * NB + t];
        float4 hA = *(const float4*)&hs[k][0];
        float4 hB = *(const float4*)&hs[k][4];
        float ha[TU] = {hA.x,hA.y,hA.z,hA.w, hB.x,hB.y,hB.z,hB.w};
        #pragma unroll
        for (int a = 0; a < TU; a++) {
            aq[a]  = fmaf(ha[a], w0, aq[a]);
            am[a]  = fmaf(ha[a], w1, am[a]);
            aqm[a] = fmaf(ha[a], w2, aqm[a]);
        }
    }
    #pragma unroll
    for (int a = 0; a < TU; a++) {
        size_t g = (size_t)(a0 + a);
        g_q[g * NB + t] = qreg[a] + aq[a] + aqm[a] * s[a];
        #pragma unroll
        for (int d = 0; d < 3; d++) {
            float val = mus[t][d][a] + am[a] * w[a][d];
            g_mu[g * 3 * NB + d * NB + t] = val;
            if (last) mu_out[g * 3 * NB + d * NB + t] = val;
        }
    }
}

// ---------------- output head ----------------
__global__ void __launch_bounds__(128) k_head(
        const float* __restrict__ o1W, const float* __restrict__ o1b,
        const float* __restrict__ o2W, const float* __restrict__ o2b,
        const float* __restrict__ o3W, const float* __restrict__ o3b,
        const int* __restrict__ idx_m, float* __restrict__ y) {
    __shared__ float qs[TH][NB];
    __shared__ float h1[TH][NB];
    __shared__ float h2[TH][NB];
    int t  = threadIdx.x;
    int a0 = blockIdx.x * TH;
    #pragma unroll
    for (int a = 0; a < TH; a++) qs[a][t] = g_q[(size_t)(a0 + a) * NB + t];
    __syncthreads();

    float acc[TH];
    float b = o1b[t];
    #pragma unroll
    for (int a = 0; a < TH; a++) acc[a] = b;
    for (int k = 0; k < NB; k++) {
        float w = o1W[k * NB + t];
        #pragma unroll
        for (int a = 0; a < TH; a++) acc[a] += qs[a][k] * w;
    }
    #pragma unroll
    for (int a = 0; a < TH; a++) h1[a][t] = silu_f(acc[a]);
    __syncthreads();

    b = o2b[t];
    #pragma unroll
    for (int a = 0; a < TH; a++) acc[a] = b;
    for (int k = 0; k < NB; k++) {
        float w = o2W[k * NB + t];
        #pragma unroll
        for (int a = 0; a < TH; a++) acc[a] += h1[a][k] * w;
    }
    #pragma unroll
    for (int a = 0; a < TH; a++) h2[a][t] = silu_f(acc[a]);
    __syncthreads();

    if (t < TH) {
        float sum = o3b[0];
        for (int k = 0; k < NB; k++) sum += h2[t][k] * o3W[k];
        atomicAdd(&y[idx_m[a0 + t]], sum);
    }
}

// ---------------- launch ----------------
extern "C" void kernel_launch(void* const* d_in, const int* in_sizes, int n_in,
                              void* d_out, int out_size) {
    const float* positions = (const float*)d_in[0];
    const float* emb  = (const float*)d_in[1];
    const float* fW   = (const float*)d_in[2];
    const float* fb   = (const float*)d_in[3];
    const float* ic1W = (const float*)d_in[4];
    const float* ic1b = (const float*)d_in[5];
    const float* ic2W = (const float*)d_in[6];
    const float* ic2b = (const float*)d_in[7];
    const float* mixW = (const float*)d_in[8];
    const float* c1W  = (const float*)d_in[9];
    const float* c1b  = (const float*)d_in[10];
    const float* c2W  = (const float*)d_in[11];
    const float* c2b  = (const float*)d_in[12];
    const float* o1W  = (const float*)d_in[13];
    const float* o1b  = (const float*)d_in[14];
    const float* o2W  = (const float*)d_in[15];
    const float* o2b  = (const float*)d_in[16];
    const float* o3W  = (const float*)d_in[17];
    const float* o3b  = (const float*)d_in[18];
    const int* z      = (const int*)d_in[19];
    const int* idx_i  = (const int*)d_in[20];
    const int* idx_j  = (const int*)d_in[21];
    const int* idx_m  = (const int*)d_in[22];
    float* out = (float*)d_out;   // layout: y[64], then mu[10000*3*128]

    k_init_edges<<<(N_EDGES + 255) / 256, 256>>>(positions, idx_i, idx_j);
    k_zero_cnt<<<(N_ATOMS + 255) / 256, 256>>>();
    k_hist<<<(N_EDGES + 255) / 256, 256>>>(idx_i);
    k_scan<<<1, 1024>>>();
    k_fill<<<(N_EDGES + 255) / 256, 256>>>(idx_i, idx_j);
    k_filters<<<N_EDGES / EB, 128>>>(fW, fb);
    k_init_atoms<<<N_ATOMS, 128>>>(emb, z, out);

    for (int it = 0; it < NI; it++) {
        k_atoms_x<<<N_ATOMS / TX, 128>>>(ic1W, ic1b, ic2W, ic2b, it);
        k_gather<<<N_ATOMS / 8, 256>>>(it);
        k_atoms_update<<<N_ATOMS / TU, 128>>>(mixW, c1W, c1b, c2W, c2b,
                                              it, it == NI - 1, out + BATCH);
    }

    k_head<<<N_ATOMS / TH, 128>>>(o1W, o1b, o2W, o2b, o3W, o3b, idx_m, out);
}

// round 6
// speedup vs baseline: 2.2295x; 1.1987x over previous
#include <cuda_runtime.h>
#include <cuda_fp16.h>
#include <math.h>

#define N_ATOMS 10000
#define N_EDGES 150000
#define NB 128
#define NI 3
#define NF (NI * 3 * NB)     // 1152 filter cols
#define N_RBF 20
#define CUTOFF 5.0f
#define EPSV 1e-8f
#define BATCH 64
#define EB 8                 // edges per filter-precompute block
#define TX 16                // atoms per block, k_atoms_x
#define PX 20                // padded row for TX
#define TU 8                 // atoms per block, k_atoms_update
#define PU 12                // padded row for TU
#define TH 8                 // atoms per block, k_head

typedef unsigned long long u64;

// ---------------- device scratch (static, no allocation) ----------------
__device__ float  g_q   [N_ATOMS * NB];
__device__ float  g_mu  [N_ATOMS * 3 * NB];
__device__ float  g_x   [N_ATOMS * 3 * NB];
__device__ float  g_dq  [N_ATOMS * NB];
__device__ float  g_dmu [N_ATOMS * 3 * NB];
__device__ float  g_phif[N_EDGES * N_RBF];
__device__ float  g_fc  [N_EDGES];
__device__ float4 g_dir4[N_EDGES];
__device__ __half g_filt[(size_t)N_EDGES * NF];     // filters (fp16) in CSR-slot order
// CSR by destination atom (idx_i)
__device__ int    g_cnt [N_ATOMS];
__device__ int    g_ofs [N_ATOMS + 1];
__device__ int    g_cur [N_ATOMS];
__device__ int    g_slot[N_EDGES];
__device__ int    g_pj  [N_EDGES];
__device__ float4 g_pdir[N_EDGES];

// ---------------- packed f32x2 helpers (FFMA2 path, sm_103a) ----------------
__device__ __forceinline__ u64 pk2(float lo, float hi) {
    u64 r; asm("mov.b64 %0, {%1, %2};" : "=l"(r) : "f"(lo), "f"(hi)); return r;
}
__device__ __forceinline__ float2 upk2(u64 v) {
    float2 f; asm("mov.b64 {%0, %1}, %2;" : "=f"(f.x), "=f"(f.y) : "l"(v)); return f;
}
__device__ __forceinline__ u64 fma2v(u64 a, u64 b, u64 c) {
    u64 d; asm("fma.rn.f32x2 %0, %1, %2, %3;" : "=l"(d) : "l"(a), "l"(b), "l"(c)); return d;
}
__device__ __forceinline__ u64 mul2v(u64 a, u64 b) {
    u64 d; asm("mul.rn.f32x2 %0, %1, %2;" : "=l"(d) : "l"(a), "l"(b)); return d;
}

__device__ __forceinline__ float silu_f(float v) {
    return v / (1.0f + expf(-v));
}

// ---------------- edge geometry precompute ----------------
__global__ void k_init_edges(const float* __restrict__ pos,
                             const int* __restrict__ idx_i,
                             const int* __restrict__ idx_j) {
    int e = blockIdx.x * blockDim.x + threadIdx.x;
    if (e >= N_EDGES) return;
    int i = idx_i[e], j = idx_j[e];
    float rx = pos[j * 3 + 0] - pos[i * 3 + 0];
    float ry = pos[j * 3 + 1] - pos[i * 3 + 1];
    float rz = pos[j * 3 + 2] - pos[i * 3 + 2];
    float d  = sqrtf(rx * rx + ry * ry + rz * rz);
    float inv = 1.0f / d;
    g_dir4[e] = make_float4(rx * inv, ry * inv, rz * inv, 0.0f);
    float fc = (d < CUTOFF) ? 0.5f * (cosf(d * (float)M_PI / CUTOFF) + 1.0f) : 0.0f;
    g_fc[e] = fc;
    const float width = CUTOFF / (float)(N_RBF - 1);
    const float coeff = -0.5f / (width * width);
    #pragma unroll
    for (int r = 0; r < N_RBF; r++) {
        float dd = d - (float)r * width;
        g_phif[e * N_RBF + r] = expf(coeff * dd * dd) * fc;
    }
}

// ---------------- CSR build ----------------
__global__ void k_zero_cnt() {
    int a = blockIdx.x * blockDim.x + threadIdx.x;
    if (a < N_ATOMS) g_cnt[a] = 0;
}
__global__ void k_hist(const int* __restrict__ idx_i) {
    int e = blockIdx.x * blockDim.x + threadIdx.x;
    if (e < N_EDGES) atomicAdd(&g_cnt[idx_i[e]], 1);
}
__global__ void __launch_bounds__(1024) k_scan() {
    __shared__ int partial[1024];
    int t = threadIdx.x;
    int base = t * 10;
    int local[10];
    int s = 0;
    #pragma unroll
    for (int k = 0; k < 10; k++) {
        int idx = base + k;
        int c = (idx < N_ATOMS) ? g_cnt[idx] : 0;
        local[k] = s;
        s += c;
    }
    partial[t] = s;
    __syncthreads();
    for (int off = 1; off < 1024; off <<= 1) {
        int v = partial[t];
        int u = (t >= off) ? partial[t - off] : 0;
        __syncthreads();
        partial[t] = v + u;
        __syncthreads();
    }
    int pre = (t > 0) ? partial[t - 1] : 0;
    #pragma unroll
    for (int k = 0; k < 10; k++) {
        int idx = base + k;
        if (idx < N_ATOMS) {
            int o = pre + local[k];
            g_ofs[idx] = o;
            g_cur[idx] = o;
        }
    }
    if (t == 1023) g_ofs[N_ATOMS] = partial[1023];
}
__global__ void k_fill(const int* __restrict__ idx_i,
                       const int* __restrict__ idx_j) {
    int e = blockIdx.x * blockDim.x + threadIdx.x;
    if (e < N_EDGES) {
        int pos = atomicAdd(&g_cur[idx_i[e]], 1);
        g_slot[e] = pos;
        g_pj[pos] = idx_j[e];
        g_pdir[pos] = g_dir4[e];
    }
}

// ---------------- dense filter precompute into CSR-slot rows (fp16, f32x2) ---
__global__ void __launch_bounds__(128) k_filters(const float* __restrict__ fW,
                                                 const float* __restrict__ fb) {
    __shared__ __align__(16) float ps[N_RBF][EB];   // [r][edge]
    __shared__ float fcs[EB];
    __shared__ int   slots[EB];
    int e0 = blockIdx.x * EB;
    int t  = threadIdx.x;
    for (int idx = t; idx < EB * N_RBF; idx += 128) {
        int a = idx / N_RBF, r = idx % N_RBF;
        ps[r][a] = g_phif[(size_t)(e0 + a) * N_RBF + r];
    }
    if (t < EB) {
        fcs[t] = g_fc[e0 + t];
        slots[t] = g_slot[e0 + t];
    }
    __syncthreads();

    u64 fcp[EB / 2];
    int slt[EB];
    #pragma unroll
    for (int p = 0; p < EB / 2; p++) fcp[p] = pk2(fcs[2 * p], fcs[2 * p + 1]);
    #pragma unroll
    for (int a = 0; a < EB; a++) slt[a] = slots[a];

    #pragma unroll 1
    for (int grp = 0; grp < NF / 128; grp++) {
        int c = grp * 128 + t;
        float bias = fb[c];
        u64 bp = pk2(bias, bias);
        u64 acc[EB / 2];
        #pragma unroll
        for (int p = 0; p < EB / 2; p++) acc[p] = mul2v(fcp[p], bp);
        #pragma unroll
        for (int r = 0; r < N_RBF; r++) {
            float w = fW[r * NF + c];
            u64 wp = pk2(w, w);
            const u64* pr = (const u64*)&ps[r][0];
            #pragma unroll
            for (int p = 0; p < EB / 2; p++) acc[p] = fma2v(pr[p], wp, acc[p]);
        }
        #pragma unroll
        for (int p = 0; p < EB / 2; p++) {
            float2 f = upk2(acc[p]);
            g_filt[(size_t)slt[2 * p] * NF + c]     = __float2half_rn(f.x);
            g_filt[(size_t)slt[2 * p + 1] * NF + c] = __float2half_rn(f.y);
        }
    }
}

// ---------------- atom init ----------------
__global__ void k_init_atoms(const float* __restrict__ emb,
                             const int* __restrict__ z,
                             float* __restrict__ y_out) {
    int a = blockIdx.x;
    int t = threadIdx.x;
    g_q[a * NB + t] = emb[z[a] * NB + t];
    #pragma unroll
    for (int d = 0; d < 3; d++)
        g_mu[a * 3 * NB + d * NB + t] = 0.0f;
    if (a == 0 && t < BATCH) y_out[t] = 0.0f;
}

// ---------------- per-atom input MLP (f32x2 packed atom pairs) ---------------
__global__ void __launch_bounds__(128) k_atoms_x(
        const float* __restrict__ ic1W, const float* __restrict__ ic1b,
        const float* __restrict__ ic2W, const float* __restrict__ ic2b,
        int it) {
    __shared__ __align__(16) float qs[NB][PX];
    __shared__ __align__(16) float hs[NB][PX];
    int t  = threadIdx.x;
    int a0 = blockIdx.x * TX;

    #pragma unroll
    for (int a = 0; a < TX; a++)
        qs[t][a] = g_q[(size_t)(a0 + a) * NB + t];
    __syncthreads();

    const float* W1 = ic1W + (size_t)it * NB * NB;
    float b1 = ic1b[it * NB + t];
    u64 acc[TX / 2];
    u64 b1p = pk2(b1, b1);
    #pragma unroll
    for (int p = 0; p < TX / 2; p++) acc[p] = b1p;
    for (int k = 0; k < NB; k++) {
        float w = W1[k * NB + t];
        u64 wp = pk2(w, w);
        const ulonglong2* q2 = (const ulonglong2*)&qs[k][0];
        #pragma unroll
        for (int p4 = 0; p4 < TX / 4; p4++) {
            ulonglong2 u = q2[p4];
            acc[2 * p4]     = fma2v(u.x, wp, acc[2 * p4]);
            acc[2 * p4 + 1] = fma2v(u.y, wp, acc[2 * p4 + 1]);
        }
    }
    #pragma unroll
    for (int p = 0; p < TX / 2; p++) {
        float2 f = upk2(acc[p]);
        hs[t][2 * p]     = silu_f(f.x);
        hs[t][2 * p + 1] = silu_f(f.y);
    }
    __syncthreads();

    const float* W2 = ic2W + (size_t)it * NB * 3 * NB;
    float b20 = ic2b[it * 3 * NB + t];
    float b21 = ic2b[it * 3 * NB + NB + t];
    float b22 = ic2b[it * 3 * NB + 2 * NB + t];
    u64 c0[TX / 2], c1[TX / 2], c2[TX / 2];
    u64 b20p = pk2(b20, b20), b21p = pk2(b21, b21), b22p = pk2(b22, b22);
    #pragma unroll
    for (int p = 0; p < TX / 2; p++) { c0[p] = b20p; c1[p] = b21p; c2[p] = b22p; }
    for (int k = 0; k < NB; k++) {
        float w0 = W2[k * 384 + t];
        float w1 = W2[k * 384 + NB + t];
        float w2 = W2[k * 384 + 2 * NB + t];
        u64 w0p = pk2(w0, w0), w1p = pk2(w1, w1), w2p = pk2(w2, w2);
        const ulonglong2* h2 = (const ulonglong2*)&hs[k][0];
        #pragma unroll
        for (int p4 = 0; p4 < TX / 4; p4++) {
            ulonglong2 u = h2[p4];
            c0[2 * p4]     = fma2v(u.x, w0p, c0[2 * p4]);
            c0[2 * p4 + 1] = fma2v(u.y, w0p, c0[2 * p4 + 1]);
            c1[2 * p4]     = fma2v(u.x, w1p, c1[2 * p4]);
            c1[2 * p4 + 1] = fma2v(u.y, w1p, c1[2 * p4 + 1]);
            c2[2 * p4]     = fma2v(u.x, w2p, c2[2 * p4]);
            c2[2 * p4 + 1] = fma2v(u.y, w2p, c2[2 * p4 + 1]);
        }
    }
    #pragma unroll
    for (int p = 0; p < TX / 2; p++) {
        float2 f0 = upk2(c0[p]);
        float2 f1 = upk2(c1[p]);
        float2 f2 = upk2(c2[p]);
        size_t ga = (size_t)(a0 + 2 * p) * 384;
        size_t gb = (size_t)(a0 + 2 * p + 1) * 384;
        g_x[ga + t] = f0.x;           g_x[gb + t] = f0.y;
        g_x[ga + NB + t] = f1.x;      g_x[gb + NB + t] = f1.y;
        g_x[ga + 2 * NB + t] = f2.x;  g_x[gb + 2 * NB + t] = f2.y;
    }
}

// ---------------- edge gather: warp per atom, f32x2 packed features ----------
__global__ void __launch_bounds__(256) k_gather(int it) {
    int warp = threadIdx.x >> 5;
    int lane = threadIdx.x & 31;
    int i = blockIdx.x * 8 + warp;
    int beg = g_ofs[i], end = g_ofs[i + 1];

    u64 mq0 = 0, mq1 = 0;
    u64 m0a = 0, m0b = 0, m1a = 0, m1b = 0, m2a = 0, m2b = 0;

    const int itofs = it * 384;   // in half units
    for (int k = beg; k < end; k++) {
        int j = __ldg(g_pj + k);
        float4 d4 = g_pdir[k];
        const __half* fe = g_filt + (size_t)k * NF + itofs;
        uint2 h0 = ((const uint2*)fe)[lane];
        uint2 h1 = ((const uint2*)fe)[32 + lane];
        uint2 h2 = ((const uint2*)fe)[64 + lane];
        float2 w0lo = __half22float2(*(__half2*)&h0.x);
        float2 w0hi = __half22float2(*(__half2*)&h0.y);
        float2 w1lo = __half22float2(*(__half2*)&h1.x);
        float2 w1hi = __half22float2(*(__half2*)&h1.y);
        float2 w2lo = __half22float2(*(__half2*)&h2.x);
        float2 w2hi = __half22float2(*(__half2*)&h2.y);
        u64 w0x = pk2(w0lo.x, w0lo.y), w0y = pk2(w0hi.x, w0hi.y);
        u64 w1x = pk2(w1lo.x, w1lo.y), w1y = pk2(w1hi.x, w1hi.y);
        u64 w2x = pk2(w2lo.x, w2lo.y), w2y = pk2(w2hi.x, w2hi.y);

        const ulonglong2* xj = (const ulonglong2*)(g_x + (size_t)j * 384);
        ulonglong2 x0 = xj[lane];
        ulonglong2 x1 = xj[32 + lane];
        ulonglong2 x2 = xj[64 + lane];
        const ulonglong2* muj = (const ulonglong2*)(g_mu + (size_t)j * 384);
        ulonglong2 u0 = muj[lane];
        ulonglong2 u1 = muj[32 + lane];
        ulonglong2 u2 = muj[64 + lane];

        mq0 = fma2v(w0x, x0.x, mq0);
        mq1 = fma2v(w0y, x0.y, mq1);
        u64 vR0 = mul2v(w1x, x1.x), vR1 = mul2v(w1y, x1.y);
        u64 vM0 = mul2v(w2x, x2.x), vM1 = mul2v(w2y, x2.y);
        u64 dxp = pk2(d4.x, d4.x), dyp = pk2(d4.y, d4.y), dzp = pk2(d4.z, d4.z);
        m0a = fma2v(vR0, dxp, fma2v(vM0, u0.x, m0a));
        m0b = fma2v(vR1, dxp, fma2v(vM1, u0.y, m0b));
        m1a = fma2v(vR0, dyp, fma2v(vM0, u1.x, m1a));
        m1b = fma2v(vR1, dyp, fma2v(vM1, u1.y, m1b));
        m2a = fma2v(vR0, dzp, fma2v(vM0, u2.x, m2a));
        m2b = fma2v(vR1, dzp, fma2v(vM1, u2.y, m2b));
    }
    ulonglong2 o;
    o.x = mq0; o.y = mq1;
    ((ulonglong2*)(g_dq + (size_t)i * NB))[lane] = o;
    ulonglong2* dmu = (ulonglong2*)(g_dmu + (size_t)i * 3 * NB);
    o.x = m0a; o.y = m0b; dmu[lane]      = o;
    o.x = m1a; o.y = m1b; dmu[32 + lane] = o;
    o.x = m2a; o.y = m2b; dmu[64 + lane] = o;
}

// ---------------- per-atom update (f32x2 packed atom pairs) ------------------
__global__ void __launch_bounds__(128) k_atoms_update(
        const float* __restrict__ mixW,
        const float* __restrict__ c1W, const float* __restrict__ c1b,
        const float* __restrict__ c2W, const float* __restrict__ c2b,
        int it, int last, float* __restrict__ mu_out) {
    __shared__ __align__(16) float mus[NB][3][PU];     // [k][d][a]
    __shared__ __align__(16) float ctxs[2 * NB][PU];   // [k][a]
    __shared__ __align__(16) float hs[NB][PU];         // [k][a]
    int t  = threadIdx.x;
    int a0 = blockIdx.x * TU;

    float qreg[TU];
    #pragma unroll
    for (int a = 0; a < TU; a++) {
        size_t g = (size_t)(a0 + a);
        qreg[a] = g_q[g * NB + t] + g_dq[g * NB + t];
        ctxs[t][a] = qreg[a];
        #pragma unroll
        for (int d = 0; d < 3; d++)
            mus[t][d][a] = g_mu[g * 3 * NB + d * NB + t] + g_dmu[g * 3 * NB + d * NB + t];
    }
    __syncthreads();

    const float* MW = mixW + (size_t)it * NB * 2 * NB;
    u64 v2[TU / 2][3], w2[TU / 2][3];
    #pragma unroll
    for (int p = 0; p < TU / 2; p++)
        #pragma unroll
        for (int d = 0; d < 3; d++) { v2[p][d] = 0; w2[p][d] = 0; }
    for (int k = 0; k < NB; k++) {
        float wv = MW[k * 256 + t];
        float ww = MW[k * 256 + NB + t];
        u64 wvp = pk2(wv, wv), wwp = pk2(ww, ww);
        #pragma unroll
        for (int d = 0; d < 3; d++) {
            const ulonglong2* m2 = (const ulonglong2*)&mus[k][d][0];
            ulonglong2 ua = m2[0];
            ulonglong2 ub = m2[1];
            v2[0][d] = fma2v(ua.x, wvp, v2[0][d]);
            v2[1][d] = fma2v(ua.y, wvp, v2[1][d]);
            v2[2][d] = fma2v(ub.x, wvp, v2[2][d]);
            v2[3][d] = fma2v(ub.y, wvp, v2[3][d]);
            w2[0][d] = fma2v(ua.x, wwp, w2[0][d]);
            w2[1][d] = fma2v(ua.y, wwp, w2[1][d]);
            w2[2][d] = fma2v(ub.x, wwp, w2[2][d]);
            w2[3][d] = fma2v(ub.y, wwp, w2[3][d]);
        }
    }
    float v[TU][3], w[TU][3];
    #pragma unroll
    for (int p = 0; p < TU / 2; p++)
        #pragma unroll
        for (int d = 0; d < 3; d++) {
            float2 fv = upk2(v2[p][d]);
            float2 fw = upk2(w2[p][d]);
            v[2 * p][d] = fv.x; v[2 * p + 1][d] = fv.y;
            w[2 * p][d] = fw.x; w[2 * p + 1][d] = fw.y;
        }
    float s[TU];
    #pragma unroll
    for (int a = 0; a < TU; a++) {
        float n2 = v[a][0]*v[a][0] + v[a][1]*v[a][1] + v[a][2]*v[a][2];
        float vn = sqrtf(n2 + EPSV);
        s[a] = v[a][0]*w[a][0] + v[a][1]*w[a][1] + v[a][2]*w[a][2];
        ctxs[NB + t][a] = vn;
    }
    __syncthreads();

    const float* W1 = c1W + (size_t)it * 2 * NB * NB;
    float b1 = c1b[it * NB + t];
    u64 acc[TU / 2];
    u64 b1p = pk2(b1, b1);
    #pragma unroll
    for (int p = 0; p < TU / 2; p++) acc[p] = b1p;
    for (int k = 0; k < 2 * NB; k++) {
        float ww1 = W1[k * NB + t];
        u64 wp = pk2(ww1, ww1);
        const ulonglong2* c2p = (const ulonglong2*)&ctxs[k][0];
        ulonglong2 ca = c2p[0], cb = c2p[1];
        acc[0] = fma2v(ca.x, wp, acc[0]);
        acc[1] = fma2v(ca.y, wp, acc[1]);
        acc[2] = fma2v(cb.x, wp, acc[2]);
        acc[3] = fma2v(cb.y, wp, acc[3]);
    }
    #pragma unroll
    for (int p = 0; p < TU / 2; p++) {
        float2 f = upk2(acc[p]);
        hs[t][2 * p]     = silu_f(f.x);
        hs[t][2 * p + 1] = silu_f(f.y);
    }
    __syncthreads();

    const float* W2 = c2W + (size_t)it * NB * 3 * NB;
    float b20 = c2b[it * 3 * NB + t];
    float b21 = c2b[it * 3 * NB + NB + t];
    float b22 = c2b[it * 3 * NB + 2 * NB + t];
    u64 aq2[TU / 2], am2[TU / 2], aqm2[TU / 2];
    u64 b20p = pk2(b20, b20), b21p = pk2(b21, b21), b22p = pk2(b22, b22);
    #pragma unroll
    for (int p = 0; p < TU / 2; p++) { aq2[p] = b20p; am2[p] = b21p; aqm2[p] = b22p; }
    for (int k = 0; k < NB; k++) {
        float w0 = W2[k * 384 + t];
        float w1 = W2[k * 384 + NB + t];
        float w2w = W2[k * 384 + 2 * NB + t];
        u64 w0p = pk2(w0, w0), w1p = pk2(w1, w1), w2p = pk2(w2w, w2w);
        const ulonglong2* h2 = (const ulonglong2*)&hs[k][0];
        ulonglong2 ha = h2[0], hb = h2[1];
        aq2[0]  = fma2v(ha.x, w0p, aq2[0]);
        aq2[1]  = fma2v(ha.y, w0p, aq2[1]);
        aq2[2]  = fma2v(hb.x, w0p, aq2[2]);
        aq2[3]  = fma2v(hb.y, w0p, aq2[3]);
        am2[0]  = fma2v(ha.x, w1p, am2[0]);
        am2[1]  = fma2v(ha.y, w1p, am2[1]);
        am2[2]  = fma2v(hb.x, w1p, am2[2]);
        am2[3]  = fma2v(hb.y, w1p, am2[3]);
        aqm2[0] = fma2v(ha.x, w2p, aqm2[0]);
        aqm2[1] = fma2v(ha.y, w2p, aqm2[1]);
        aqm2[2] = fma2v(hb.x, w2p, aqm2[2]);
        aqm2[3] = fma2v(hb.y, w2p, aqm2[3]);
    }
    float aq[TU], am[TU], aqm[TU];
    #pragma unroll
    for (int p = 0; p < TU / 2; p++) {
        float2 f0 = upk2(aq2[p]);
        float2 f1 = upk2(am2[p]);
        float2 f2 = upk2(aqm2[p]);
        aq[2 * p] = f0.x;  aq[2 * p + 1] = f0.y;
        am[2 * p] = f1.x;  am[2 * p + 1] = f1.y;
        aqm[2 * p] = f2.x; aqm[2 * p + 1] = f2.y;
    }
    #pragma unroll
    for (int a = 0; a < TU; a++) {
        size_t g = (size_t)(a0 + a);
        g_q[g * NB + t] = qreg[a] + aq[a] + aqm[a] * s[a];
        #pragma unroll
        for (int d = 0; d < 3; d++) {
            float val = mus[t][d][a] + am[a] * w[a][d];
            g_mu[g * 3 * NB + d * NB + t] = val;
            if (last) mu_out[g * 3 * NB + d * NB + t] = val;
        }
    }
}

// ---------------- output head ----------------
__global__ void __launch_bounds__(128) k_head(
        const float* __restrict__ o1W, const float* __restrict__ o1b,
        const float* __restrict__ o2W, const float* __restrict__ o2b,
        const float* __restrict__ o3W, const float* __restrict__ o3b,
        const int* __restrict__ idx_m, float* __restrict__ y) {
    __shared__ float qs[TH][NB];
    __shared__ float h1[TH][NB];
    __shared__ float h2[TH][NB];
    int t  = threadIdx.x;
    int a0 = blockIdx.x * TH;
    #pragma unroll
    for (int a = 0; a < TH; a++) qs[a][t] = g_q[(size_t)(a0 + a) * NB + t];
    __syncthreads();

    float acc[TH];
    float b = o1b[t];
    #pragma unroll
    for (int a = 0; a < TH; a++) acc[a] = b;
    for (int k = 0; k < NB; k++) {
        float w = o1W[k * NB + t];
        #pragma unroll
        for (int a = 0; a < TH; a++) acc[a] += qs[a][k] * w;
    }
    #pragma unroll
    for (int a = 0; a < TH; a++) h1[a][t] = silu_f(acc[a]);
    __syncthreads();

    b = o2b[t];
    #pragma unroll
    for (int a = 0; a < TH; a++) acc[a] = b;
    for (int k = 0; k < NB; k++) {
        float w = o2W[k * NB + t];
        #pragma unroll
        for (int a = 0; a < TH; a++) acc[a] += h1[a][k] * w;
    }
    #pragma unroll
    for (int a = 0; a < TH; a++) h2[a][t] = silu_f(acc[a]);
    __syncthreads();

    if (t < TH) {
        float sum = o3b[0];
        for (int k = 0; k < NB; k++) sum += h2[t][k] * o3W[k];
        atomicAdd(&y[idx_m[a0 + t]], sum);
    }
}

// ---------------- launch ----------------
extern "C" void kernel_launch(void* const* d_in, const int* in_sizes, int n_in,
                              void* d_out, int out_size) {
    const float* positions = (const float*)d_in[0];
    const float* emb  = (const float*)d_in[1];
    const float* fW   = (const float*)d_in[2];
    const float* fb   = (const float*)d_in[3];
    const float* ic1W = (const float*)d_in[4];
    const float* ic1b = (const float*)d_in[5];
    const float* ic2W = (const float*)d_in[6];
    const float* ic2b = (const float*)d_in[7];
    const float* mixW = (const float*)d_in[8];
    const float* c1W  = (const float*)d_in[9];
    const float* c1b  = (const float*)d_in[10];
    const float* c2W  = (const float*)d_in[11];
    const float* c2b  = (const float*)d_in[12];
    const float* o1W  = (const float*)d_in[13];
    const float* o1b  = (const float*)d_in[14];
    const float* o2W  = (const float*)d_in[15];
    const float* o2b  = (const float*)d_in[16];
    const float* o3W  = (const float*)d_in[17];
    const float* o3b  = (const float*)d_in[18];
    const int* z      = (const int*)d_in[19];
    const int* idx_i  = (const int*)d_in[20];
    const int* idx_j  = (const int*)d_in[21];
    const int* idx_m  = (const int*)d_in[22];
    float* out = (float*)d_out;   // layout: y[64], then mu[10000*3*128]

    k_init_edges<<<(N_EDGES + 255) / 256, 256>>>(positions, idx_i, idx_j);
    k_zero_cnt<<<(N_ATOMS + 255) / 256, 256>>>();
    k_hist<<<(N_EDGES + 255) / 256, 256>>>(idx_i);
    k_scan<<<1, 1024>>>();
    k_fill<<<(N_EDGES + 255) / 256, 256>>>(idx_i, idx_j);
    k_filters<<<N_EDGES / EB, 128>>>(fW, fb);
    k_init_atoms<<<N_ATOMS, 128>>>(emb, z, out);

    for (int it = 0; it < NI; it++) {
        k_atoms_x<<<N_ATOMS / TX, 128>>>(ic1W, ic1b, ic2W, ic2b, it);
        k_gather<<<N_ATOMS / 8, 256>>>(it);
        k_atoms_update<<<N_ATOMS / TU, 128>>>(mixW, c1W, c1b, c2W, c2b,
                                              it, it == NI - 1, out + BATCH);
    }

    k_head<<<N_ATOMS / TH, 128>>>(o1W, o1b, o2W, o2b, o3W, o3b, idx_m, out);
}